// round 11
// baseline (speedup 1.0000x reference)
#include <cuda_runtime.h>
#include <cuda_fp16.h>
#include <math.h>
#include <stdint.h>

// Problem constants
constexpr int B_  = 32;
constexpr int T_  = 512;
constexpr int D_  = 512;
constexpr int H_  = 8;
constexpr int DH_ = 64;
constexpr int HB_ = H_ * B_;        // 256
constexpr int FF_ = 4 * D_;         // 2048

// ---------------- scratch (static device globals; allocation-free) ----------
__device__ float  g_pe [T_ * D_];
__device__ float  g_q1 [B_ * T_ * D_];              // fp32 residual
__device__ __half g_q1h[B_ * T_ * D_];
__device__ __half g_q1l[B_ * T_ * D_];
__device__ __half g_k1h[B_ * T_ * D_];
__device__ __half g_k1l[B_ * T_ * D_];
__device__ __half g_Qh [B_ * T_ * D_];
__device__ __half g_Ql [B_ * T_ * D_];
__device__ __half g_Kh [B_ * T_ * D_];
__device__ __half g_Kl [B_ * T_ * D_];
__device__ __half g_Vh [B_ * T_ * D_];
__device__ float  g_S  [(long)HB_ * T_ * T_];       // 256MB fp32 scores
__device__ float  g_cmax[HB_ * T_];
__device__ float  g_R  [B_ * T_ * D_];              // fp32 residual
__device__ __half g_Rh [B_ * T_ * D_];
__device__ __half g_H  [(long)B_ * T_ * FF_];       // hidden (fp16), 64MB
// converted weights
__device__ __half g_wqh[D_ * D_], g_wql[D_ * D_];
__device__ __half g_wkh[D_ * D_], g_wkl[D_ * D_];
__device__ __half g_wvh[D_ * D_];
__device__ __half g_f1h[D_ * FF_];
__device__ __half g_f2h[FF_ * D_];

// ---------------- helpers ---------------------------------------------------
__device__ __forceinline__ void mma16n8k16(float* c, const uint32_t* a, const uint32_t* b) {
    asm volatile(
        "mma.sync.aligned.m16n8k16.row.col.f32.f16.f16.f32 "
        "{%0,%1,%2,%3}, {%4,%5,%6,%7}, {%8,%9}, {%0,%1,%2,%3};"
        : "+f"(c[0]), "+f"(c[1]), "+f"(c[2]), "+f"(c[3])
        : "r"(a[0]), "r"(a[1]), "r"(a[2]), "r"(a[3]), "r"(b[0]), "r"(b[1]));
}
__device__ __forceinline__ void ldsm_x4(uint32_t* r, uint32_t a) {
    asm volatile("ldmatrix.sync.aligned.m8n8.x4.shared.b16 {%0,%1,%2,%3}, [%4];"
        : "=r"(r[0]), "=r"(r[1]), "=r"(r[2]), "=r"(r[3]) : "r"(a));
}
__device__ __forceinline__ void ldsm_x2(uint32_t* r, uint32_t a) {
    asm volatile("ldmatrix.sync.aligned.m8n8.x2.shared.b16 {%0,%1}, [%2];"
        : "=r"(r[0]), "=r"(r[1]) : "r"(a));
}
__device__ __forceinline__ void ldsm_x2t(uint32_t* r, uint32_t a) {
    asm volatile("ldmatrix.sync.aligned.m8n8.x2.trans.shared.b16 {%0,%1}, [%2];"
        : "=r"(r[0]), "=r"(r[1]) : "r"(a));
}
__device__ __forceinline__ uint32_t smem_u32(const void* p) {
    uint32_t a;
    asm("{ .reg .u64 t; cvta.to.shared.u64 t, %1; cvt.u32.u64 %0, t; }"
        : "=r"(a) : "l"(p));
    return a;
}
// cp.async with L1 bypass (.cg): keeps L1 bandwidth free for ldmatrix
__device__ __forceinline__ void cpa16(uint32_t saddr, const void* g) {
    asm volatile("cp.async.cg.shared.global [%0], [%1], 16;"
                 :: "r"(saddr), "l"(g) : "memory");
}
#define CPA_COMMIT() asm volatile("cp.async.commit_group;" ::: "memory")
#define CPA_WAIT1()  asm volatile("cp.async.wait_group 1;" ::: "memory")
#define CPA_WAIT0()  asm volatile("cp.async.wait_group 0;" ::: "memory")

__device__ __forceinline__ void atomicMaxFloat(float* addr, float v) {
    if (v >= 0.f) atomicMax((int*)addr, __float_as_int(v));
    else          atomicMin((unsigned int*)addr, __float_as_uint(v));
}

// ============ fp16 mma.sync GEMM engine v4 (ldmatrix + cp.async) ============
// Block tile 128x128, BK=32, 256 threads (8 warps: nWM=2, nWN=4; WM=64, WN=32).
// A row-major [M][K] fp16. B: TBB=0 -> [K][N]; TBB=1 -> [N][K].
// SPLIT: hi/lo planes, 3 MMAs. OUT: 0=fp32; 1=fp16 hi; 2=fp16 hi+lo.
// CM: fused column-max atomics. DUAL: blockIdx.z==1 selects alternate tensors.
// NS: pipeline depth (2 = preload-all fast path, requires K/BK <= 2; 3 = ring).
template<bool TBB, bool SPLIT, int OUT, bool CM, int NS, bool DUAL>
__global__ void __launch_bounds__(256, 2) mma4(
    const __half* __restrict__ Ah_g, const __half* __restrict__ Al_g,
    long sA1, long sA2, int lda,
    const __half* __restrict__ Bh_g, const __half* __restrict__ Bl_g,
    long sB1, long sB2, int ldb,
    float* Cf, __half* Chi, __half* Clo, long sC1, long sC2, int ldc,
    const float* __restrict__ Res, long sR1, long sR2, int ldres,
    float* cmaxp,
    int nb2, int K, float alpha, int relu,
    const __half* A2h, const __half* A2l,
    const __half* B2h, const __half* B2l,
    __half* C2hi, __half* C2lo)
{
    constexpr int BK  = 32;
    constexpr int AP  = 40;                 // A pitch (halves)
    constexpr int APL = 128 * AP;
    constexpr int NSP = SPLIT ? 2 : 1;
    constexpr int ASZ = NSP * APL;
    constexpr int BP  = 136;                // [K][N] B pitch
    constexpr int BPL = TBB ? APL : BK * BP;
    constexpr int BSZ = NSP * BPL;
    constexpr int STG = ASZ + BSZ;
    constexpr int MT  = 4;
    constexpr int NT  = 4;

    extern __shared__ __half smh[];
    const uint32_t sbase = smem_u32(smh);

    int z  = blockIdx.z;
    if (DUAL && z == 1) {
        Ah_g = A2h; Al_g = A2l; Bh_g = B2h; Bl_g = B2l;
        Chi = C2hi; Clo = C2lo;
    } else {
        int i1 = z / nb2, i2 = z % nb2;
        Ah_g += i1 * sA1 + i2 * sA2;
        if (SPLIT) Al_g += i1 * sA1 + i2 * sA2;
        Bh_g += i1 * sB1 + i2 * sB2;
        if (SPLIT) Bl_g += i1 * sB1 + i2 * sB2;
        if (OUT == 0) Cf  += i1 * sC1 + i2 * sC2;
        if (OUT >= 1) Chi += i1 * sC1 + i2 * sC2;
        if (OUT == 2) Clo += i1 * sC1 + i2 * sC2;
        if (Res) Res += i1 * sR1 + i2 * sR2;
        if (CM)  cmaxp += (long)z * ldc;
    }

    const int tid  = threadIdx.x;
    const int lane = tid & 31;
    const int wid  = tid >> 5;
    const int warp_m = wid & 1;
    const int warp_n = wid >> 1;
    const int row0 = blockIdx.y * 128;
    const int col0 = blockIdx.x * 128;
    const int frow = lane >> 2, fcol = lane & 3;

    float acc[MT][NT][4];
    #pragma unroll
    for (int i = 0; i < MT; i++)
        #pragma unroll
        for (int j = 0; j < NT; j++)
            #pragma unroll
            for (int q = 0; q < 4; q++) acc[i][j][q] = 0.f;

    auto load_stage = [&](int st, int k0) {
        uint32_t sA = sbase + (uint32_t)(st * STG) * 2;
        #pragma unroll
        for (int i = 0; i < 2 * NSP; i++) {
            int idx = i * 256 + tid;
            int plane = idx >> 9;
            int rem = idx & 511;
            int row = rem >> 2, c8 = (rem & 3) * 8;
            const __half* g = (SPLIT && plane ? Al_g : Ah_g)
                            + (long)(row0 + row) * lda + k0 + c8;
            cpa16(sA + (uint32_t)(plane * APL + row * AP + c8) * 2, g);
        }
        uint32_t sB = sbase + (uint32_t)(st * STG + ASZ) * 2;
        if (TBB) {
            #pragma unroll
            for (int i = 0; i < 2 * NSP; i++) {
                int idx = i * 256 + tid;
                int plane = idx >> 9;
                int rem = idx & 511;
                int row = rem >> 2, c8 = (rem & 3) * 8;
                const __half* g = (SPLIT && plane ? Bl_g : Bh_g)
                                + (long)(col0 + row) * ldb + k0 + c8;
                cpa16(sB + (uint32_t)(plane * APL + row * AP + c8) * 2, g);
            }
        } else {
            #pragma unroll
            for (int i = 0; i < 2 * NSP; i++) {
                int idx = i * 256 + tid;
                int plane = idx >> 9;
                int rem = idx & 511;
                int row = rem >> 4, c8 = (rem & 15) * 8;
                const __half* g = (SPLIT && plane ? Bl_g : Bh_g)
                                + (long)(k0 + row) * ldb + col0 + c8;
                cpa16(sB + (uint32_t)(plane * BPL + row * BP + c8) * 2, g);
            }
        }
    };

    auto compute = [&](int st) {
        const uint32_t aB = sbase + (uint32_t)(st * STG) * 2;
        const uint32_t bB = aB + (uint32_t)ASZ * 2;
        #pragma unroll
        for (int ks = 0; ks < 2; ks++) {
            const int kk = ks * 16;
            uint32_t af[MT][4], bh[NT][2];
            #pragma unroll
            for (int i = 0; i < MT; i++)
                ldsm_x4(af[i], aB + (uint32_t)((warp_m * 64 + i * 16 + (lane & 15)) * AP
                                               + kk + (lane >> 4) * 8) * 2);
            #pragma unroll
            for (int j = 0; j < NT; j++) {
                if (TBB)
                    ldsm_x2(bh[j], bB + (uint32_t)((warp_n * 32 + j * 8 + (lane & 7)) * AP
                                                   + kk + ((lane >> 3) & 1) * 8) * 2);
                else
                    ldsm_x2t(bh[j], bB + (uint32_t)((kk + (lane & 15)) * BP
                                                    + warp_n * 32 + j * 8) * 2);
            }
            #pragma unroll
            for (int i = 0; i < MT; i++)
                #pragma unroll
                for (int j = 0; j < NT; j++)
                    mma16n8k16(acc[i][j], af[i], bh[j]);
            if (SPLIT) {
                uint32_t b2[NT][2];
                #pragma unroll
                for (int j = 0; j < NT; j++) {
                    if (TBB)
                        ldsm_x2(b2[j], bB + (uint32_t)(APL + (warp_n * 32 + j * 8 + (lane & 7)) * AP
                                                       + kk + ((lane >> 3) & 1) * 8) * 2);
                    else
                        ldsm_x2t(b2[j], bB + (uint32_t)(BPL + (kk + (lane & 15)) * BP
                                                        + warp_n * 32 + j * 8) * 2);
                }
                #pragma unroll
                for (int i = 0; i < MT; i++)
                    #pragma unroll
                    for (int j = 0; j < NT; j++)
                        mma16n8k16(acc[i][j], af[i], b2[j]);
                #pragma unroll
                for (int i = 0; i < MT; i++)
                    ldsm_x4(af[i], aB + (uint32_t)(APL + (warp_m * 64 + i * 16 + (lane & 15)) * AP
                                                   + kk + (lane >> 4) * 8) * 2);
                #pragma unroll
                for (int i = 0; i < MT; i++)
                    #pragma unroll
                    for (int j = 0; j < NT; j++)
                        mma16n8k16(acc[i][j], af[i], bh[j]);
            }
        }
    };

    const int NTL = K / BK;
    if (NS == 3) {
        load_stage(0, 0);   CPA_COMMIT();
        load_stage(1, BK);  CPA_COMMIT();
        for (int kt = 0; kt < NTL; kt++) {
            CPA_WAIT1();
            __syncthreads();
            if (kt + 2 < NTL) load_stage((kt + 2) % 3, (kt + 2) * BK);
            CPA_COMMIT();
            compute(kt % 3);
        }
    } else {
        // NS == 2 fast path: K/BK <= 2 guaranteed by call sites.
        // Preload everything, one wait, one barrier, compute straight through.
        load_stage(0, 0);
        if (NTL > 1) load_stage(1, BK);
        CPA_COMMIT();
        CPA_WAIT0();
        __syncthreads();
        compute(0);
        if (NTL > 1) compute(1);
    }

    // ---- epilogue ----
    float colm[NT][2];
    if (CM) {
        #pragma unroll
        for (int j = 0; j < NT; j++) { colm[j][0] = -INFINITY; colm[j][1] = -INFINITY; }
    }
    #pragma unroll
    for (int i = 0; i < MT; i++) {
        #pragma unroll
        for (int j = 0; j < NT; j++) {
            int r = row0 + warp_m * 64 + i * 16 + frow;
            int c = col0 + warp_n * 32 + j * 8 + 2 * fcol;
            #pragma unroll
            for (int h = 0; h < 2; h++) {
                long rr = r + h * 8;
                float v0 = acc[i][j][2 * h] * alpha;
                float v1 = acc[i][j][2 * h + 1] * alpha;
                if (Res) {
                    v0 += Res[rr * (long)ldres + c];
                    v1 += Res[rr * (long)ldres + c + 1];
                }
                if (relu) { v0 = fmaxf(v0, 0.f); v1 = fmaxf(v1, 0.f); }
                if (CM) {
                    colm[j][0] = fmaxf(colm[j][0], v0);
                    colm[j][1] = fmaxf(colm[j][1], v1);
                }
                if (OUT == 0)
                    *(float2*)&Cf[rr * (long)ldc + c] = make_float2(v0, v1);
                if (OUT >= 1) {
                    __half h0 = __float2half_rn(v0), h1 = __float2half_rn(v1);
                    *(__half2*)&Chi[rr * (long)ldc + c] = __halves2half2(h0, h1);
                    if (OUT == 2) {
                        __half l0 = __float2half_rn(v0 - __half2float(h0));
                        __half l1 = __float2half_rn(v1 - __half2float(h1));
                        *(__half2*)&Clo[rr * (long)ldc + c] = __halves2half2(l0, l1);
                    }
                }
            }
        }
    }
    if (CM) {
        #pragma unroll
        for (int j = 0; j < NT; j++) {
            #pragma unroll
            for (int s = 4; s <= 16; s <<= 1) {
                colm[j][0] = fmaxf(colm[j][0], __shfl_xor_sync(0xffffffffu, colm[j][0], s));
                colm[j][1] = fmaxf(colm[j][1], __shfl_xor_sync(0xffffffffu, colm[j][1], s));
            }
        }
        if (frow == 0) {
            #pragma unroll
            for (int j = 0; j < NT; j++) {
                int c = col0 + warp_n * 32 + j * 8 + 2 * fcol;
                atomicMaxFloat(&cmaxp[c],     colm[j][0]);
                atomicMaxFloat(&cmaxp[c + 1], colm[j][1]);
            }
        }
    }
}

constexpr int smem4(bool TBB, bool SPLIT, int NS) {
    int APL = 128 * 40, NSP = SPLIT ? 2 : 1;
    int BPL = TBB ? APL : 32 * 136;
    return 2 * NS * NSP * (APL + BPL);
}

// ============ fused two-pass softmax + AV (fp16 MMA) ========================
// grid (T/128, HB), 256 threads. p tile [128][72] halves; V tile [64][72].
constexpr int FS_PB   = 0;
constexpr int FS_VB   = FS_PB + 2 * 128 * 72 * 2;      // 36864
constexpr int FS_CM   = FS_VB + 2 * 64 * 72 * 2;       // 55296
constexpr int FS_MM   = FS_CM + 512 * 4;               // 57344
constexpr int FS_SS   = FS_MM + 128 * 4;               // 57856
constexpr int FS_SMEM = FS_SS + 128 * 4;               // 58368

__global__ __launch_bounds__(256, 2) void fsav_kernel(
    const float* __restrict__ S,
    const float* __restrict__ cmax,
    const __half* __restrict__ Vh,
    const float* __restrict__ q1f,
    const int* __restrict__ qmasks,
    float* __restrict__ Rf, __half* __restrict__ Rh)
{
    extern __shared__ char fs[];
    float* cm  = (float*)(fs + FS_CM);
    float* smM = (float*)(fs + FS_MM);
    float* smS = (float*)(fs + FS_SS);
    const uint32_t sbase = smem_u32(fs);

    const int tid = threadIdx.x, lane = tid & 31, wid = tid >> 5;
    const int q0 = blockIdx.x * 128;
    const int z  = blockIdx.y;
    const int hh = z / B_, b = z % B_;
    const float*  Sz = S + (long)z * T_ * T_;
    const __half* Vz = Vh + (long)b * T_ * D_ + hh * DH_;
    const float*  Qz = q1f + (long)b * T_ * D_ + hh * DH_;
    float*  Rfz = Rf + (long)b * T_ * D_ + hh * DH_;
    __half* Rhz = Rh + (long)b * T_ * D_ + hh * DH_;
    const int qlim = qmasks[b];

    cm[tid]       = cmax[z * T_ + tid];
    cm[tid + 256] = cmax[z * T_ + tid + 256];
    __syncthreads();

    // ---- phase 1: per-row max & sum (one warp per row) ----
    for (int it = 0; it < 16; it++) {
        int r = it * 8 + wid;
        const float* Srow = Sz + (long)(q0 + r) * T_;
        float x[16];
        #pragma unroll
        for (int seg = 0; seg < 4; seg++) {
            float4 v = *(const float4*)(Srow + seg * 128 + lane * 4);
            int c = seg * 128 + lane * 4;
            x[seg * 4 + 0] = v.x - cm[c + 0];
            x[seg * 4 + 1] = v.y - cm[c + 1];
            x[seg * 4 + 2] = v.z - cm[c + 2];
            x[seg * 4 + 3] = v.w - cm[c + 3];
        }
        float m = x[0];
        #pragma unroll
        for (int j = 1; j < 16; j++) m = fmaxf(m, x[j]);
        #pragma unroll
        for (int o = 16; o; o >>= 1) m = fmaxf(m, __shfl_xor_sync(0xffffffffu, m, o));
        float s = 0.f;
        #pragma unroll
        for (int j = 0; j < 16; j++) s += expf(x[j] - m);
        #pragma unroll
        for (int o = 16; o; o >>= 1) s += __shfl_xor_sync(0xffffffffu, s, o);
        if (lane == 0) { smM[r] = m; smS[r] = s; }
    }
    __syncthreads();

    // ---- phase 2: stream k-tiles of 64: regenerate p (fp16), MMA with V ----
    const int warp_m = wid & 3, warp_n = wid >> 2;  // WM=32 (MT=2), WN=32 (NT=4)
    const int frow = lane >> 2, fcol = lane & 3;

    float acc[2][4][4];
    #pragma unroll
    for (int i = 0; i < 2; i++)
        #pragma unroll
        for (int j = 0; j < 4; j++)
            #pragma unroll
            for (int q = 0; q < 4; q++) acc[i][j][q] = 0.f;

    auto loadV = [&](int buf, int k0) {
        #pragma unroll
        for (int i = 0; i < 2; i++) {
            int idx = i * 256 + tid;
            int row = idx >> 3, c8 = (idx & 7) * 8;
            cpa16(sbase + (uint32_t)(FS_VB + (buf * 64 * 72 + row * 72 + c8) * 2),
                  Vz + (long)(k0 + row) * D_ + c8);
        }
    };
    auto genP = [&](int buf, int k0) {
        __half* pt = (__half*)(fs + FS_PB) + buf * 128 * 72;
        #pragma unroll
        for (int pass = 0; pass < 8; pass++) {
            int r = pass * 16 + (tid >> 4);
            int c4 = (tid & 15) * 4;
            float4 v = *(const float4*)(Sz + (long)(q0 + r) * T_ + k0 + c4);
            float mm = smM[r];
            __half2 p0 = __floats2half2_rn(expf(v.x - cm[k0 + c4 + 0] - mm),
                                           expf(v.y - cm[k0 + c4 + 1] - mm));
            __half2 p1 = __floats2half2_rn(expf(v.z - cm[k0 + c4 + 2] - mm),
                                           expf(v.w - cm[k0 + c4 + 3] - mm));
            *(__half2*)&pt[r * 72 + c4]     = p0;
            *(__half2*)&pt[r * 72 + c4 + 2] = p1;
        }
    };

    loadV(0, 0); CPA_COMMIT();

    for (int kt = 0; kt < 8; kt++) {
        int buf = kt & 1;
        genP(buf, kt * 64);
        CPA_WAIT0();
        __syncthreads();
        if (kt + 1 < 8) { loadV(buf ^ 1, (kt + 1) * 64); CPA_COMMIT(); }
        const uint32_t pB = sbase + (uint32_t)(FS_PB + buf * 128 * 72 * 2);
        const uint32_t vB = sbase + (uint32_t)(FS_VB + buf * 64 * 72 * 2);
        #pragma unroll
        for (int ks = 0; ks < 4; ks++) {
            const int kk = ks * 16;
            uint32_t af[2][4], bf[4][2];
            #pragma unroll
            for (int i = 0; i < 2; i++)
                ldsm_x4(af[i], pB + (uint32_t)((warp_m * 32 + i * 16 + (lane & 15)) * 72
                                               + kk + (lane >> 4) * 8) * 2);
            #pragma unroll
            for (int j = 0; j < 4; j++)
                ldsm_x2t(bf[j], vB + (uint32_t)((kk + (lane & 15)) * 72
                                                + warp_n * 32 + j * 8) * 2);
            #pragma unroll
            for (int i = 0; i < 2; i++)
                #pragma unroll
                for (int j = 0; j < 4; j++)
                    mma16n8k16(acc[i][j], af[i], bf[j]);
        }
        __syncthreads();
    }

    // ---- epilogue: scale by qmask/sum, add residual, write fp32 + fp16 ----
    #pragma unroll
    for (int i = 0; i < 2; i++) {
        #pragma unroll
        for (int j = 0; j < 4; j++) {
            int rloc = warp_m * 32 + i * 16 + frow;
            int c = warp_n * 32 + j * 8 + 2 * fcol;
            #pragma unroll
            for (int h = 0; h < 2; h++) {
                int rr = rloc + h * 8;
                float inv = ((q0 + rr) < qlim ? 1.f : 0.f) / smS[rr];
                long off = (long)(q0 + rr) * D_ + c;
                float v0 = acc[i][j][2 * h] * inv + Qz[off];
                float v1 = acc[i][j][2 * h + 1] * inv + Qz[off + 1];
                *(float2*)&Rfz[off] = make_float2(v0, v1);
                *(__half2*)&Rhz[off] = __floats2half2_rn(v0, v1);
            }
        }
    }
}

// ---------------- positional encoding (fp64 to match numpy) -----------------
__global__ void pe_kernel(float* __restrict__ pe) {
    int idx = blockIdx.x * blockDim.x + threadIdx.x;
    if (idx >= T_ * D_) return;
    int t = idx / D_;
    int d = idx % D_;
    double ang = (double)t * exp(-(2.0 * (double)d / (double)D_) * log(10000.0));
    double v = (d & 1) ? cos(ang) : sin(ang);
    pe[idx] = (float)(v * sqrt((double)D_));
}

__global__ void addpe2_kernel(const float* __restrict__ q, const float* __restrict__ pe,
                              float* __restrict__ q1f,
                              __half* __restrict__ q1h, __half* __restrict__ q1l,
                              __half* __restrict__ k1h, __half* __restrict__ k1l) {
    long idx = (long)blockIdx.x * blockDim.x + threadIdx.x;
    long td = idx % ((long)T_ * D_);
    float p = pe[td];
    float a = q[idx] + p;
    q1f[idx] = a;
    __half ah = __float2half_rn(a);
    q1h[idx] = ah;
    q1l[idx] = __float2half_rn(a - __half2float(ah));
    float bb = a + p;                      // k1 = q1 + pe (source bug kept)
    __half bh = __float2half_rn(bb);
    k1h[idx] = bh;
    k1l[idx] = __float2half_rn(bb - __half2float(bh));
}

// single fused conversion kernel: all weights + cmax init
__global__ void cvt_all_kernel(const float* __restrict__ wq, const float* __restrict__ wk,
                               const float* __restrict__ wv, const float* __restrict__ f1,
                               const float* __restrict__ f2,
                               __half* __restrict__ wqh, __half* __restrict__ wql,
                               __half* __restrict__ wkh, __half* __restrict__ wkl,
                               __half* __restrict__ wvh,
                               __half* __restrict__ f1h, __half* __restrict__ f2h,
                               float* __restrict__ cmaxp) {
    constexpr int DD = D_ * D_;
    constexpr int DF = D_ * FF_;
    int i = blockIdx.x * blockDim.x + threadIdx.x;
    if (i < DD) {
        float x = wq[i];
        __half h = __float2half_rn(x);
        wqh[i] = h;
        wql[i] = __float2half_rn(x - __half2float(h));
    } else if (i < 2 * DD) {
        int j = i - DD;
        float x = wk[j];
        __half h = __float2half_rn(x);
        wkh[j] = h;
        wkl[j] = __float2half_rn(x - __half2float(h));
    } else if (i < 3 * DD) {
        int j = i - 2 * DD;
        wvh[j] = __float2half_rn(wv[j]);
    } else if (i < 3 * DD + DF) {
        int j = i - 3 * DD;
        f1h[j] = __float2half_rn(f1[j]);
    } else if (i < 3 * DD + 2 * DF) {
        int j = i - 3 * DD - DF;
        f2h[j] = __float2half_rn(f2[j]);
    } else if (i < 3 * DD + 2 * DF + HB_ * T_) {
        cmaxp[i - 3 * DD - 2 * DF] = -INFINITY;
    }
}

// ---------------- launch -----------------------------------------------------
extern "C" void kernel_launch(void* const* d_in, const int* in_sizes, int n_in,
                              void* d_out, int out_size) {
    const float* queries = (const float*)d_in[0];
    const int*   qmasks  = (const int*)d_in[2];
    const float* W_Q = (const float*)d_in[4];
    const float* W_K = (const float*)d_in[5];
    const float* W_V = (const float*)d_in[6];
    const float* fw1 = (const float*)d_in[7];
    const float* fw2 = (const float*)d_in[8];
    float* out = (float*)d_out;

    float *pe, *q1f, *S, *cmax, *R;
    __half *q1h, *q1l, *k1h, *k1l, *Qh, *Ql, *Kh, *Kl, *Vh, *Rh, *Hd;
    __half *wqh, *wql, *wkh, *wkl, *wvh, *f1h, *f2h;
    cudaGetSymbolAddress((void**)&pe,  g_pe);
    cudaGetSymbolAddress((void**)&q1f, g_q1);
    cudaGetSymbolAddress((void**)&q1h, g_q1h);
    cudaGetSymbolAddress((void**)&q1l, g_q1l);
    cudaGetSymbolAddress((void**)&k1h, g_k1h);
    cudaGetSymbolAddress((void**)&k1l, g_k1l);
    cudaGetSymbolAddress((void**)&Qh,  g_Qh);
    cudaGetSymbolAddress((void**)&Ql,  g_Ql);
    cudaGetSymbolAddress((void**)&Kh,  g_Kh);
    cudaGetSymbolAddress((void**)&Kl,  g_Kl);
    cudaGetSymbolAddress((void**)&Vh,  g_Vh);
    cudaGetSymbolAddress((void**)&S,   g_S);
    cudaGetSymbolAddress((void**)&cmax, g_cmax);
    cudaGetSymbolAddress((void**)&R,   g_R);
    cudaGetSymbolAddress((void**)&Rh,  g_Rh);
    cudaGetSymbolAddress((void**)&Hd,  g_H);
    cudaGetSymbolAddress((void**)&wqh, g_wqh);
    cudaGetSymbolAddress((void**)&wql, g_wql);
    cudaGetSymbolAddress((void**)&wkh, g_wkh);
    cudaGetSymbolAddress((void**)&wkl, g_wkl);
    cudaGetSymbolAddress((void**)&wvh, g_wvh);
    cudaGetSymbolAddress((void**)&f1h, g_f1h);
    cudaGetSymbolAddress((void**)&f2h, g_f2h);

    const long TD = (long)T_ * D_;
    const long TT = (long)T_ * T_;

    constexpr int SM_PLAIN = smem4(false, false, 3);  // 56832
    constexpr int SM_SPL3  = smem4(false, true,  3);  // 113664 (2 CTAs: 227328)
    constexpr int SM_SPL1  = smem4(true,  true,  2);  // 81920

    cudaFuncSetAttribute((const void*)mma4<false, true,  2, false, 3, true>,
                         cudaFuncAttributeMaxDynamicSharedMemorySize, SM_SPL3);
    cudaFuncSetAttribute((const void*)mma4<true,  true,  0, true,  2, false>,
                         cudaFuncAttributeMaxDynamicSharedMemorySize, SM_SPL1);
    cudaFuncSetAttribute((const void*)mma4<false, false, 1, false, 3, false>,
                         cudaFuncAttributeMaxDynamicSharedMemorySize, SM_PLAIN);
    cudaFuncSetAttribute((const void*)mma4<false, false, 0, false, 3, false>,
                         cudaFuncAttributeMaxDynamicSharedMemorySize, SM_PLAIN);
    cudaFuncSetAttribute((const void*)fsav_kernel,
                         cudaFuncAttributeMaxDynamicSharedMemorySize, FS_SMEM);

    // 1) posenc + all conversions (+cmax init)
    pe_kernel<<<(T_ * D_ + 255) / 256, 256>>>(pe);
    addpe2_kernel<<<(B_ * T_ * D_) / 256, 256>>>(queries, pe, q1f, q1h, q1l, k1h, k1l);
    {
        int n = 3 * D_ * D_ + 2 * D_ * FF_ + HB_ * T_;
        cvt_all_kernel<<<(n + 255) / 256, 256>>>(W_Q, W_K, W_V, fw1, fw2,
                                                 wqh, wql, wkh, wkl, wvh, f1h, f2h, cmax);
    }

    // 2) Q and K projections batched in one DUAL launch (fp16 split, 3-stage)
    {
        dim3 g(D_ / 128, (B_ * T_) / 128, 2);
        mma4<false, true, 2, false, 3, true><<<g, 256, SM_SPL3>>>(
            q1h, q1l, 0, 0, D_, wqh, wql, 0, 0, D_,
            nullptr, Qh, Ql, 0, 0, D_, nullptr, 0, 0, 0, nullptr, 1, D_, 1.f, 0,
            k1h, k1l, wkh, wkl, Kh, Kl);
    }

    // 3) V projection: V = Kp @ W_V (bug kept) -> fp16 (3-stage)
    {
        dim3 g(D_ / 128, (B_ * T_) / 128, 1);
        mma4<false, false, 1, false, 3, false><<<g, 256, SM_PLAIN>>>(
            Kh, nullptr, 0, 0, D_, wvh, nullptr, 0, 0, D_,
            nullptr, Vh, nullptr, 0, 0, D_, nullptr, 0, 0, 0, nullptr, 1, D_, 1.f, 0,
            nullptr, nullptr, nullptr, nullptr, nullptr, nullptr);
    }

    // 4) scores (fp16 split, B=[N][K]) -> fp32 S + fused column-max atomics
    //    K=64 -> NTL=2 -> NS=2 preload-all fast path
    {
        dim3 g(T_ / 128, T_ / 128, HB_);
        mma4<true, true, 0, true, 2, false><<<g, 256, SM_SPL1>>>(
            Qh, Ql, DH_, TD, D_,
            Kh, Kl, DH_, TD, D_,
            S, nullptr, nullptr, (long)B_ * TT, TT, T_,
            nullptr, 0, 0, 0, cmax,
            B_, DH_, 0.125f, 0,
            nullptr, nullptr, nullptr, nullptr, nullptr, nullptr);
    }

    // 5) fused two-pass softmax + AV: R = softmax(S - cmax)*qmask @ V + q1
    {
        dim3 g(T_ / 128, HB_);
        fsav_kernel<<<g, 256, FS_SMEM>>>(S, cmax, Vh, q1f, qmasks, R, Rh);
    }

    // 6) FFN1: hidden = relu(R @ fw1) -> fp16 (3-stage)
    {
        dim3 g(FF_ / 128, (B_ * T_) / 128, 1);
        mma4<false, false, 1, false, 3, false><<<g, 256, SM_PLAIN>>>(
            Rh, nullptr, 0, 0, D_, f1h, nullptr, 0, 0, FF_,
            nullptr, Hd, nullptr, 0, 0, FF_, nullptr, 0, 0, 0, nullptr, 1, D_, 1.f, 1,
            nullptr, nullptr, nullptr, nullptr, nullptr, nullptr);
    }

    // 7) FFN2: out = R + hidden @ fw2 -> fp32 (3-stage)
    {
        dim3 g(D_ / 128, (B_ * T_) / 128, 1);
        mma4<false, false, 0, false, 3, false><<<g, 256, SM_PLAIN>>>(
            Hd, nullptr, 0, 0, FF_, f2h, nullptr, 0, 0, D_,
            out, nullptr, nullptr, 0, 0, D_, R, 0, 0, D_, nullptr, 1, FF_, 1.f, 0,
            nullptr, nullptr, nullptr, nullptr, nullptr, nullptr);
    }
}

// round 12
// speedup vs baseline: 1.0251x; 1.0251x over previous
#include <cuda_runtime.h>
#include <cuda_fp16.h>
#include <math.h>
#include <stdint.h>

// Problem constants
constexpr int B_  = 32;
constexpr int T_  = 512;
constexpr int D_  = 512;
constexpr int H_  = 8;
constexpr int DH_ = 64;
constexpr int HB_ = H_ * B_;        // 256
constexpr int FF_ = 4 * D_;         // 2048

// ---------------- scratch (static device globals; allocation-free) ----------
__device__ float  g_pe [T_ * D_];
__device__ float  g_q1 [B_ * T_ * D_];              // fp32 residual
__device__ __half g_q1h[B_ * T_ * D_];
__device__ __half g_q1l[B_ * T_ * D_];
__device__ __half g_k1h[B_ * T_ * D_];
__device__ __half g_k1l[B_ * T_ * D_];
__device__ __half g_Qh [B_ * T_ * D_];
__device__ __half g_Ql [B_ * T_ * D_];
__device__ __half g_Kh [B_ * T_ * D_];
__device__ __half g_Kl [B_ * T_ * D_];
__device__ __half g_Vh [B_ * T_ * D_];
__device__ float  g_S  [(long)HB_ * T_ * T_];       // 256MB fp32 scores
__device__ float  g_cmax[HB_ * T_];
__device__ float  g_R  [B_ * T_ * D_];              // fp32 residual
__device__ __half g_Rh [B_ * T_ * D_];
__device__ __half g_H  [(long)B_ * T_ * FF_];       // hidden (fp16), 64MB
// converted weights
__device__ __half g_wqh[D_ * D_], g_wql[D_ * D_];
__device__ __half g_wkh[D_ * D_], g_wkl[D_ * D_];
__device__ __half g_wvh[D_ * D_];
__device__ __half g_f1h[D_ * FF_];
__device__ __half g_f2h[FF_ * D_];

// ---------------- helpers ---------------------------------------------------
__device__ __forceinline__ void mma16n8k16(float* c, const uint32_t* a, const uint32_t* b) {
    asm volatile(
        "mma.sync.aligned.m16n8k16.row.col.f32.f16.f16.f32 "
        "{%0,%1,%2,%3}, {%4,%5,%6,%7}, {%8,%9}, {%0,%1,%2,%3};"
        : "+f"(c[0]), "+f"(c[1]), "+f"(c[2]), "+f"(c[3])
        : "r"(a[0]), "r"(a[1]), "r"(a[2]), "r"(a[3]), "r"(b[0]), "r"(b[1]));
}
__device__ __forceinline__ void ldsm_x4(uint32_t* r, uint32_t a) {
    asm volatile("ldmatrix.sync.aligned.m8n8.x4.shared.b16 {%0,%1,%2,%3}, [%4];"
        : "=r"(r[0]), "=r"(r[1]), "=r"(r[2]), "=r"(r[3]) : "r"(a));
}
__device__ __forceinline__ void ldsm_x2(uint32_t* r, uint32_t a) {
    asm volatile("ldmatrix.sync.aligned.m8n8.x2.shared.b16 {%0,%1}, [%2];"
        : "=r"(r[0]), "=r"(r[1]) : "r"(a));
}
__device__ __forceinline__ void ldsm_x2t(uint32_t* r, uint32_t a) {
    asm volatile("ldmatrix.sync.aligned.m8n8.x2.trans.shared.b16 {%0,%1}, [%2];"
        : "=r"(r[0]), "=r"(r[1]) : "r"(a));
}
__device__ __forceinline__ uint32_t smem_u32(const void* p) {
    uint32_t a;
    asm("{ .reg .u64 t; cvta.to.shared.u64 t, %1; cvt.u32.u64 %0, t; }"
        : "=r"(a) : "l"(p));
    return a;
}
// cp.async with L1 bypass (.cg): keeps L1 bandwidth free for ldmatrix
__device__ __forceinline__ void cpa16(uint32_t saddr, const void* g) {
    asm volatile("cp.async.cg.shared.global [%0], [%1], 16;"
                 :: "r"(saddr), "l"(g) : "memory");
}
#define CPA_COMMIT() asm volatile("cp.async.commit_group;" ::: "memory")
#define CPA_WAIT1()  asm volatile("cp.async.wait_group 1;" ::: "memory")
#define CPA_WAIT0()  asm volatile("cp.async.wait_group 0;" ::: "memory")

__device__ __forceinline__ void atomicMaxFloat(float* addr, float v) {
    if (v >= 0.f) atomicMax((int*)addr, __float_as_int(v));
    else          atomicMin((unsigned int*)addr, __float_as_uint(v));
}

// ============ fp16 mma.sync GEMM engine v4 (ldmatrix + cp.async) ============
// Block tile 128x128, BK=32, 256 threads (8 warps: nWM=2, nWN=4; WM=64, WN=32).
// A row-major [M][K] fp16. B: TBB=0 -> [K][N]; TBB=1 -> [N][K].
// SPLIT: hi/lo planes, 3 MMAs. OUT: 0=fp32; 1=fp16 hi; 2=fp16 hi+lo.
// CM: fused column-max atomics. DUAL: blockIdx.z==1 selects alternate tensors.
// NS: pipeline depth (2 = preload-all fast path, requires K/BK <= 2; 3 = ring).
template<bool TBB, bool SPLIT, int OUT, bool CM, int NS, bool DUAL>
__global__ void __launch_bounds__(256, 2) mma4(
    const __half* __restrict__ Ah_g, const __half* __restrict__ Al_g,
    long sA1, long sA2, int lda,
    const __half* __restrict__ Bh_g, const __half* __restrict__ Bl_g,
    long sB1, long sB2, int ldb,
    float* Cf, __half* Chi, __half* Clo, long sC1, long sC2, int ldc,
    const float* __restrict__ Res, long sR1, long sR2, int ldres,
    float* cmaxp,
    int nb2, int K, float alpha, int relu,
    const __half* A2h, const __half* A2l,
    const __half* B2h, const __half* B2l,
    __half* C2hi, __half* C2lo)
{
    constexpr int BK  = 32;
    constexpr int AP  = 40;                 // A pitch (halves)
    constexpr int APL = 128 * AP;
    constexpr int NSP = SPLIT ? 2 : 1;
    constexpr int ASZ = NSP * APL;
    constexpr int BP  = 136;                // [K][N] B pitch
    constexpr int BPL = TBB ? APL : BK * BP;
    constexpr int BSZ = NSP * BPL;
    constexpr int STG = ASZ + BSZ;
    constexpr int MT  = 4;
    constexpr int NT  = 4;

    extern __shared__ __half smh[];
    const uint32_t sbase = smem_u32(smh);

    int z  = blockIdx.z;
    if (DUAL && z == 1) {
        Ah_g = A2h; Al_g = A2l; Bh_g = B2h; Bl_g = B2l;
        Chi = C2hi; Clo = C2lo;
    } else {
        int i1 = z / nb2, i2 = z % nb2;
        Ah_g += i1 * sA1 + i2 * sA2;
        if (SPLIT) Al_g += i1 * sA1 + i2 * sA2;
        Bh_g += i1 * sB1 + i2 * sB2;
        if (SPLIT) Bl_g += i1 * sB1 + i2 * sB2;
        if (OUT == 0) Cf  += i1 * sC1 + i2 * sC2;
        if (OUT >= 1) Chi += i1 * sC1 + i2 * sC2;
        if (OUT == 2) Clo += i1 * sC1 + i2 * sC2;
        if (Res) Res += i1 * sR1 + i2 * sR2;
        if (CM)  cmaxp += (long)z * ldc;
    }

    const int tid  = threadIdx.x;
    const int lane = tid & 31;
    const int wid  = tid >> 5;
    const int warp_m = wid & 1;
    const int warp_n = wid >> 1;
    const int row0 = blockIdx.y * 128;
    const int col0 = blockIdx.x * 128;
    const int frow = lane >> 2, fcol = lane & 3;

    float acc[MT][NT][4];
    #pragma unroll
    for (int i = 0; i < MT; i++)
        #pragma unroll
        for (int j = 0; j < NT; j++)
            #pragma unroll
            for (int q = 0; q < 4; q++) acc[i][j][q] = 0.f;

    auto load_stage = [&](int st, int k0) {
        uint32_t sA = sbase + (uint32_t)(st * STG) * 2;
        #pragma unroll
        for (int i = 0; i < 2 * NSP; i++) {
            int idx = i * 256 + tid;
            int plane = idx >> 9;
            int rem = idx & 511;
            int row = rem >> 2, c8 = (rem & 3) * 8;
            const __half* g = (SPLIT && plane ? Al_g : Ah_g)
                            + (long)(row0 + row) * lda + k0 + c8;
            cpa16(sA + (uint32_t)(plane * APL + row * AP + c8) * 2, g);
        }
        uint32_t sB = sbase + (uint32_t)(st * STG + ASZ) * 2;
        if (TBB) {
            #pragma unroll
            for (int i = 0; i < 2 * NSP; i++) {
                int idx = i * 256 + tid;
                int plane = idx >> 9;
                int rem = idx & 511;
                int row = rem >> 2, c8 = (rem & 3) * 8;
                const __half* g = (SPLIT && plane ? Bl_g : Bh_g)
                                + (long)(col0 + row) * ldb + k0 + c8;
                cpa16(sB + (uint32_t)(plane * APL + row * AP + c8) * 2, g);
            }
        } else {
            #pragma unroll
            for (int i = 0; i < 2 * NSP; i++) {
                int idx = i * 256 + tid;
                int plane = idx >> 9;
                int rem = idx & 511;
                int row = rem >> 4, c8 = (rem & 15) * 8;
                const __half* g = (SPLIT && plane ? Bl_g : Bh_g)
                                + (long)(k0 + row) * ldb + col0 + c8;
                cpa16(sB + (uint32_t)(plane * BPL + row * BP + c8) * 2, g);
            }
        }
    };

    auto compute = [&](int st) {
        const uint32_t aB = sbase + (uint32_t)(st * STG) * 2;
        const uint32_t bB = aB + (uint32_t)ASZ * 2;
        #pragma unroll
        for (int ks = 0; ks < 2; ks++) {
            const int kk = ks * 16;
            uint32_t af[MT][4], bh[NT][2];
            #pragma unroll
            for (int i = 0; i < MT; i++)
                ldsm_x4(af[i], aB + (uint32_t)((warp_m * 64 + i * 16 + (lane & 15)) * AP
                                               + kk + (lane >> 4) * 8) * 2);
            #pragma unroll
            for (int j = 0; j < NT; j++) {
                if (TBB)
                    ldsm_x2(bh[j], bB + (uint32_t)((warp_n * 32 + j * 8 + (lane & 7)) * AP
                                                   + kk + ((lane >> 3) & 1) * 8) * 2);
                else
                    ldsm_x2t(bh[j], bB + (uint32_t)((kk + (lane & 15)) * BP
                                                    + warp_n * 32 + j * 8) * 2);
            }
            #pragma unroll
            for (int i = 0; i < MT; i++)
                #pragma unroll
                for (int j = 0; j < NT; j++)
                    mma16n8k16(acc[i][j], af[i], bh[j]);
            if (SPLIT) {
                uint32_t b2[NT][2];
                #pragma unroll
                for (int j = 0; j < NT; j++) {
                    if (TBB)
                        ldsm_x2(b2[j], bB + (uint32_t)(APL + (warp_n * 32 + j * 8 + (lane & 7)) * AP
                                                       + kk + ((lane >> 3) & 1) * 8) * 2);
                    else
                        ldsm_x2t(b2[j], bB + (uint32_t)(BPL + (kk + (lane & 15)) * BP
                                                        + warp_n * 32 + j * 8) * 2);
                }
                #pragma unroll
                for (int i = 0; i < MT; i++)
                    #pragma unroll
                    for (int j = 0; j < NT; j++)
                        mma16n8k16(acc[i][j], af[i], b2[j]);
                #pragma unroll
                for (int i = 0; i < MT; i++)
                    ldsm_x4(af[i], aB + (uint32_t)(APL + (warp_m * 64 + i * 16 + (lane & 15)) * AP
                                                   + kk + (lane >> 4) * 8) * 2);
                #pragma unroll
                for (int i = 0; i < MT; i++)
                    #pragma unroll
                    for (int j = 0; j < NT; j++)
                        mma16n8k16(acc[i][j], af[i], bh[j]);
            }
        }
    };

    const int NTL = K / BK;
    if (NS == 3) {
        load_stage(0, 0);   CPA_COMMIT();
        load_stage(1, BK);  CPA_COMMIT();
        for (int kt = 0; kt < NTL; kt++) {
            CPA_WAIT1();
            __syncthreads();
            if (kt + 2 < NTL) load_stage((kt + 2) % 3, (kt + 2) * BK);
            CPA_COMMIT();
            compute(kt % 3);
        }
    } else {
        // NS == 2 fast path: K/BK <= 2 guaranteed by call sites.
        load_stage(0, 0);
        if (NTL > 1) load_stage(1, BK);
        CPA_COMMIT();
        CPA_WAIT0();
        __syncthreads();
        compute(0);
        if (NTL > 1) compute(1);
    }

    // ---- epilogue ----
    float colm[NT][2];
    if (CM) {
        #pragma unroll
        for (int j = 0; j < NT; j++) { colm[j][0] = -INFINITY; colm[j][1] = -INFINITY; }
    }
    #pragma unroll
    for (int i = 0; i < MT; i++) {
        #pragma unroll
        for (int j = 0; j < NT; j++) {
            int r = row0 + warp_m * 64 + i * 16 + frow;
            int c = col0 + warp_n * 32 + j * 8 + 2 * fcol;
            #pragma unroll
            for (int h = 0; h < 2; h++) {
                long rr = r + h * 8;
                float v0 = acc[i][j][2 * h] * alpha;
                float v1 = acc[i][j][2 * h + 1] * alpha;
                if (Res) {
                    v0 += Res[rr * (long)ldres + c];
                    v1 += Res[rr * (long)ldres + c + 1];
                }
                if (relu) { v0 = fmaxf(v0, 0.f); v1 = fmaxf(v1, 0.f); }
                if (CM) {
                    colm[j][0] = fmaxf(colm[j][0], v0);
                    colm[j][1] = fmaxf(colm[j][1], v1);
                }
                if (OUT == 0)
                    *(float2*)&Cf[rr * (long)ldc + c] = make_float2(v0, v1);
                if (OUT >= 1) {
                    __half h0 = __float2half_rn(v0), h1 = __float2half_rn(v1);
                    *(__half2*)&Chi[rr * (long)ldc + c] = __halves2half2(h0, h1);
                    if (OUT == 2) {
                        __half l0 = __float2half_rn(v0 - __half2float(h0));
                        __half l1 = __float2half_rn(v1 - __half2float(h1));
                        *(__half2*)&Clo[rr * (long)ldc + c] = __halves2half2(l0, l1);
                    }
                }
            }
        }
    }
    if (CM) {
        #pragma unroll
        for (int j = 0; j < NT; j++) {
            #pragma unroll
            for (int s = 4; s <= 16; s <<= 1) {
                colm[j][0] = fmaxf(colm[j][0], __shfl_xor_sync(0xffffffffu, colm[j][0], s));
                colm[j][1] = fmaxf(colm[j][1], __shfl_xor_sync(0xffffffffu, colm[j][1], s));
            }
        }
        if (frow == 0) {
            #pragma unroll
            for (int j = 0; j < NT; j++) {
                int c = col0 + warp_n * 32 + j * 8 + 2 * fcol;
                atomicMaxFloat(&cmaxp[c],     colm[j][0]);
                atomicMaxFloat(&cmaxp[c + 1], colm[j][1]);
            }
        }
    }
}

constexpr int smem4(bool TBB, bool SPLIT, int NS) {
    int APL = 128 * 40, NSP = SPLIT ? 2 : 1;
    int BPL = TBB ? APL : 32 * 136;
    return 2 * NS * NSP * (APL + BPL);
}

// ============ fused two-pass softmax + AV (fp16 MMA), qmask row-skip ========
// grid (T/128, HB), 256 threads. p tile [128][72] halves; V tile [64][72].
// Rows q >= qmasks[b] produce attn rows that are zeroed by the qmask —
// their exp/max/sum are skipped entirely (output is residual-only, identical).
constexpr int FS_PB   = 0;
constexpr int FS_VB   = FS_PB + 2 * 128 * 72 * 2;      // 36864
constexpr int FS_CM   = FS_VB + 2 * 64 * 72 * 2;       // 55296
constexpr int FS_MM   = FS_CM + 512 * 4;               // 57344
constexpr int FS_SS   = FS_MM + 128 * 4;               // 57856
constexpr int FS_SMEM = FS_SS + 128 * 4;               // 58368

__global__ __launch_bounds__(256, 2) void fsav_kernel(
    const float* __restrict__ S,
    const float* __restrict__ cmax,
    const __half* __restrict__ Vh,
    const float* __restrict__ q1f,
    const int* __restrict__ qmasks,
    float* __restrict__ Rf, __half* __restrict__ Rh)
{
    extern __shared__ char fs[];
    float* cm  = (float*)(fs + FS_CM);
    float* smM = (float*)(fs + FS_MM);
    float* smS = (float*)(fs + FS_SS);
    const uint32_t sbase = smem_u32(fs);

    const int tid = threadIdx.x, lane = tid & 31, wid = tid >> 5;
    const int q0 = blockIdx.x * 128;
    const int z  = blockIdx.y;
    const int hh = z / B_, b = z % B_;
    const float*  Sz = S + (long)z * T_ * T_;
    const __half* Vz = Vh + (long)b * T_ * D_ + hh * DH_;
    const float*  Qz = q1f + (long)b * T_ * D_ + hh * DH_;
    float*  Rfz = Rf + (long)b * T_ * D_ + hh * DH_;
    __half* Rhz = Rh + (long)b * T_ * D_ + hh * DH_;
    const int qlim = qmasks[b];

    cm[tid]       = cmax[z * T_ + tid];
    cm[tid + 256] = cmax[z * T_ + tid + 256];
    __syncthreads();

    // ---- phase 1: per-row max & sum (one warp per row); skip masked rows ----
    for (int it = 0; it < 16; it++) {
        int r = it * 8 + wid;
        if (q0 + r >= qlim) {
            if (lane == 0) { smM[r] = 0.f; smS[r] = 1.f; }  // benign (row zeroed)
            continue;
        }
        const float* Srow = Sz + (long)(q0 + r) * T_;
        float x[16];
        #pragma unroll
        for (int seg = 0; seg < 4; seg++) {
            float4 v = *(const float4*)(Srow + seg * 128 + lane * 4);
            int c = seg * 128 + lane * 4;
            x[seg * 4 + 0] = v.x - cm[c + 0];
            x[seg * 4 + 1] = v.y - cm[c + 1];
            x[seg * 4 + 2] = v.z - cm[c + 2];
            x[seg * 4 + 3] = v.w - cm[c + 3];
        }
        float m = x[0];
        #pragma unroll
        for (int j = 1; j < 16; j++) m = fmaxf(m, x[j]);
        #pragma unroll
        for (int o = 16; o; o >>= 1) m = fmaxf(m, __shfl_xor_sync(0xffffffffu, m, o));
        float s = 0.f;
        #pragma unroll
        for (int j = 0; j < 16; j++) s += expf(x[j] - m);
        #pragma unroll
        for (int o = 16; o; o >>= 1) s += __shfl_xor_sync(0xffffffffu, s, o);
        if (lane == 0) { smM[r] = m; smS[r] = s; }
    }
    __syncthreads();

    // ---- phase 2: stream k-tiles of 64: regenerate p (fp16), MMA with V ----
    const int warp_m = wid & 3, warp_n = wid >> 2;  // WM=32 (MT=2), WN=32 (NT=4)
    const int frow = lane >> 2, fcol = lane & 3;

    float acc[2][4][4];
    #pragma unroll
    for (int i = 0; i < 2; i++)
        #pragma unroll
        for (int j = 0; j < 4; j++)
            #pragma unroll
            for (int q = 0; q < 4; q++) acc[i][j][q] = 0.f;

    auto loadV = [&](int buf, int k0) {
        #pragma unroll
        for (int i = 0; i < 2; i++) {
            int idx = i * 256 + tid;
            int row = idx >> 3, c8 = (idx & 7) * 8;
            cpa16(sbase + (uint32_t)(FS_VB + (buf * 64 * 72 + row * 72 + c8) * 2),
                  Vz + (long)(k0 + row) * D_ + c8);
        }
    };
    auto genP = [&](int buf, int k0) {
        __half* pt = (__half*)(fs + FS_PB) + buf * 128 * 72;
        #pragma unroll
        for (int pass = 0; pass < 8; pass++) {
            int r = pass * 16 + (tid >> 4);
            int c4 = (tid & 15) * 4;
            if (q0 + r >= qlim) {
                // masked row: p = 0 (no S read, no exp)
                *(__half2*)&pt[r * 72 + c4]     = __halves2half2(__ushort_as_half(0),
                                                                 __ushort_as_half(0));
                *(__half2*)&pt[r * 72 + c4 + 2] = __halves2half2(__ushort_as_half(0),
                                                                 __ushort_as_half(0));
                continue;
            }
            float4 v = *(const float4*)(Sz + (long)(q0 + r) * T_ + k0 + c4);
            float mm = smM[r];
            __half2 p0 = __floats2half2_rn(expf(v.x - cm[k0 + c4 + 0] - mm),
                                           expf(v.y - cm[k0 + c4 + 1] - mm));
            __half2 p1 = __floats2half2_rn(expf(v.z - cm[k0 + c4 + 2] - mm),
                                           expf(v.w - cm[k0 + c4 + 3] - mm));
            *(__half2*)&pt[r * 72 + c4]     = p0;
            *(__half2*)&pt[r * 72 + c4 + 2] = p1;
        }
    };

    loadV(0, 0); CPA_COMMIT();

    for (int kt = 0; kt < 8; kt++) {
        int buf = kt & 1;
        genP(buf, kt * 64);
        CPA_WAIT0();
        __syncthreads();
        if (kt + 1 < 8) { loadV(buf ^ 1, (kt + 1) * 64); CPA_COMMIT(); }
        const uint32_t pB = sbase + (uint32_t)(FS_PB + buf * 128 * 72 * 2);
        const uint32_t vB = sbase + (uint32_t)(FS_VB + buf * 64 * 72 * 2);
        #pragma unroll
        for (int ks = 0; ks < 4; ks++) {
            const int kk = ks * 16;
            uint32_t af[2][4], bf[4][2];
            #pragma unroll
            for (int i = 0; i < 2; i++)
                ldsm_x4(af[i], pB + (uint32_t)((warp_m * 32 + i * 16 + (lane & 15)) * 72
                                               + kk + (lane >> 4) * 8) * 2);
            #pragma unroll
            for (int j = 0; j < 4; j++)
                ldsm_x2t(bf[j], vB + (uint32_t)((kk + (lane & 15)) * 72
                                                + warp_n * 32 + j * 8) * 2);
            #pragma unroll
            for (int i = 0; i < 2; i++)
                #pragma unroll
                for (int j = 0; j < 4; j++)
                    mma16n8k16(acc[i][j], af[i], bf[j]);
        }
        __syncthreads();
    }

    // ---- epilogue: scale by qmask/sum, add residual, write fp32 + fp16 ----
    #pragma unroll
    for (int i = 0; i < 2; i++) {
        #pragma unroll
        for (int j = 0; j < 4; j++) {
            int rloc = warp_m * 32 + i * 16 + frow;
            int c = warp_n * 32 + j * 8 + 2 * fcol;
            #pragma unroll
            for (int h = 0; h < 2; h++) {
                int rr = rloc + h * 8;
                float inv = ((q0 + rr) < qlim ? 1.f : 0.f) / smS[rr];
                long off = (long)(q0 + rr) * D_ + c;
                float v0 = acc[i][j][2 * h] * inv + Qz[off];
                float v1 = acc[i][j][2 * h + 1] * inv + Qz[off + 1];
                *(float2*)&Rfz[off] = make_float2(v0, v1);
                *(__half2*)&Rhz[off] = __floats2half2_rn(v0, v1);
            }
        }
    }
}

// ---------------- positional encoding (fp64 to match numpy) -----------------
__global__ void pe_kernel(float* __restrict__ pe) {
    int idx = blockIdx.x * blockDim.x + threadIdx.x;
    if (idx >= T_ * D_) return;
    int t = idx / D_;
    int d = idx % D_;
    double ang = (double)t * exp(-(2.0 * (double)d / (double)D_) * log(10000.0));
    double v = (d & 1) ? cos(ang) : sin(ang);
    pe[idx] = (float)(v * sqrt((double)D_));
}

__global__ void addpe2_kernel(const float* __restrict__ q, const float* __restrict__ pe,
                              float* __restrict__ q1f,
                              __half* __restrict__ q1h, __half* __restrict__ q1l,
                              __half* __restrict__ k1h, __half* __restrict__ k1l) {
    long idx = (long)blockIdx.x * blockDim.x + threadIdx.x;
    long td = idx % ((long)T_ * D_);
    float p = pe[td];
    float a = q[idx] + p;
    q1f[idx] = a;
    __half ah = __float2half_rn(a);
    q1h[idx] = ah;
    q1l[idx] = __float2half_rn(a - __half2float(ah));
    float bb = a + p;                      // k1 = q1 + pe (source bug kept)
    __half bh = __float2half_rn(bb);
    k1h[idx] = bh;
    k1l[idx] = __float2half_rn(bb - __half2float(bh));
}

// single fused conversion kernel: all weights + cmax init
__global__ void cvt_all_kernel(const float* __restrict__ wq, const float* __restrict__ wk,
                               const float* __restrict__ wv, const float* __restrict__ f1,
                               const float* __restrict__ f2,
                               __half* __restrict__ wqh, __half* __restrict__ wql,
                               __half* __restrict__ wkh, __half* __restrict__ wkl,
                               __half* __restrict__ wvh,
                               __half* __restrict__ f1h, __half* __restrict__ f2h,
                               float* __restrict__ cmaxp) {
    constexpr int DD = D_ * D_;
    constexpr int DF = D_ * FF_;
    int i = blockIdx.x * blockDim.x + threadIdx.x;
    if (i < DD) {
        float x = wq[i];
        __half h = __float2half_rn(x);
        wqh[i] = h;
        wql[i] = __float2half_rn(x - __half2float(h));
    } else if (i < 2 * DD) {
        int j = i - DD;
        float x = wk[j];
        __half h = __float2half_rn(x);
        wkh[j] = h;
        wkl[j] = __float2half_rn(x - __half2float(h));
    } else if (i < 3 * DD) {
        int j = i - 2 * DD;
        wvh[j] = __float2half_rn(wv[j]);
    } else if (i < 3 * DD + DF) {
        int j = i - 3 * DD;
        f1h[j] = __float2half_rn(f1[j]);
    } else if (i < 3 * DD + 2 * DF) {
        int j = i - 3 * DD - DF;
        f2h[j] = __float2half_rn(f2[j]);
    } else if (i < 3 * DD + 2 * DF + HB_ * T_) {
        cmaxp[i - 3 * DD - 2 * DF] = -INFINITY;
    }
}

// ---------------- launch -----------------------------------------------------
extern "C" void kernel_launch(void* const* d_in, const int* in_sizes, int n_in,
                              void* d_out, int out_size) {
    const float* queries = (const float*)d_in[0];
    const int*   qmasks  = (const int*)d_in[2];
    const float* W_Q = (const float*)d_in[4];
    const float* W_K = (const float*)d_in[5];
    const float* W_V = (const float*)d_in[6];
    const float* fw1 = (const float*)d_in[7];
    const float* fw2 = (const float*)d_in[8];
    float* out = (float*)d_out;

    float *pe, *q1f, *S, *cmax, *R;
    __half *q1h, *q1l, *k1h, *k1l, *Qh, *Ql, *Kh, *Kl, *Vh, *Rh, *Hd;
    __half *wqh, *wql, *wkh, *wkl, *wvh, *f1h, *f2h;
    cudaGetSymbolAddress((void**)&pe,  g_pe);
    cudaGetSymbolAddress((void**)&q1f, g_q1);
    cudaGetSymbolAddress((void**)&q1h, g_q1h);
    cudaGetSymbolAddress((void**)&q1l, g_q1l);
    cudaGetSymbolAddress((void**)&k1h, g_k1h);
    cudaGetSymbolAddress((void**)&k1l, g_k1l);
    cudaGetSymbolAddress((void**)&Qh,  g_Qh);
    cudaGetSymbolAddress((void**)&Ql,  g_Ql);
    cudaGetSymbolAddress((void**)&Kh,  g_Kh);
    cudaGetSymbolAddress((void**)&Kl,  g_Kl);
    cudaGetSymbolAddress((void**)&Vh,  g_Vh);
    cudaGetSymbolAddress((void**)&S,   g_S);
    cudaGetSymbolAddress((void**)&cmax, g_cmax);
    cudaGetSymbolAddress((void**)&R,   g_R);
    cudaGetSymbolAddress((void**)&Rh,  g_Rh);
    cudaGetSymbolAddress((void**)&Hd,  g_H);
    cudaGetSymbolAddress((void**)&wqh, g_wqh);
    cudaGetSymbolAddress((void**)&wql, g_wql);
    cudaGetSymbolAddress((void**)&wkh, g_wkh);
    cudaGetSymbolAddress((void**)&wkl, g_wkl);
    cudaGetSymbolAddress((void**)&wvh, g_wvh);
    cudaGetSymbolAddress((void**)&f1h, g_f1h);
    cudaGetSymbolAddress((void**)&f2h, g_f2h);

    const long TD = (long)T_ * D_;
    const long TT = (long)T_ * T_;

    constexpr int SM_PLAIN = smem4(false, false, 3);  // 56832
    constexpr int SM_SPL3  = smem4(false, true,  3);  // 113664 (2 CTAs: 227328)
    constexpr int SM_SPL1  = smem4(true,  true,  2);  // 81920

    cudaFuncSetAttribute((const void*)mma4<false, true,  2, false, 3, true>,
                         cudaFuncAttributeMaxDynamicSharedMemorySize, SM_SPL3);
    cudaFuncSetAttribute((const void*)mma4<true,  true,  0, true,  2, false>,
                         cudaFuncAttributeMaxDynamicSharedMemorySize, SM_SPL1);
    cudaFuncSetAttribute((const void*)mma4<false, false, 1, false, 3, false>,
                         cudaFuncAttributeMaxDynamicSharedMemorySize, SM_PLAIN);
    cudaFuncSetAttribute((const void*)mma4<false, false, 0, false, 3, false>,
                         cudaFuncAttributeMaxDynamicSharedMemorySize, SM_PLAIN);
    cudaFuncSetAttribute((const void*)fsav_kernel,
                         cudaFuncAttributeMaxDynamicSharedMemorySize, FS_SMEM);

    // 1) posenc + all conversions (+cmax init)
    pe_kernel<<<(T_ * D_ + 255) / 256, 256>>>(pe);
    addpe2_kernel<<<(B_ * T_ * D_) / 256, 256>>>(queries, pe, q1f, q1h, q1l, k1h, k1l);
    {
        int n = 3 * D_ * D_ + 2 * D_ * FF_ + HB_ * T_;
        cvt_all_kernel<<<(n + 255) / 256, 256>>>(W_Q, W_K, W_V, fw1, fw2,
                                                 wqh, wql, wkh, wkl, wvh, f1h, f2h, cmax);
    }

    // 2) Q and K projections batched in one DUAL launch (fp16 split, 3-stage)
    {
        dim3 g(D_ / 128, (B_ * T_) / 128, 2);
        mma4<false, true, 2, false, 3, true><<<g, 256, SM_SPL3>>>(
            q1h, q1l, 0, 0, D_, wqh, wql, 0, 0, D_,
            nullptr, Qh, Ql, 0, 0, D_, nullptr, 0, 0, 0, nullptr, 1, D_, 1.f, 0,
            k1h, k1l, wkh, wkl, Kh, Kl);
    }

    // 3) V projection: V = Kp @ W_V (bug kept) -> fp16 (3-stage)
    {
        dim3 g(D_ / 128, (B_ * T_) / 128, 1);
        mma4<false, false, 1, false, 3, false><<<g, 256, SM_PLAIN>>>(
            Kh, nullptr, 0, 0, D_, wvh, nullptr, 0, 0, D_,
            nullptr, Vh, nullptr, 0, 0, D_, nullptr, 0, 0, 0, nullptr, 1, D_, 1.f, 0,
            nullptr, nullptr, nullptr, nullptr, nullptr, nullptr);
    }

    // 4) scores (fp16 split, B=[N][K]) -> fp32 S + fused column-max atomics
    //    K=64 -> NTL=2 -> NS=2 preload-all fast path
    {
        dim3 g(T_ / 128, T_ / 128, HB_);
        mma4<true, true, 0, true, 2, false><<<g, 256, SM_SPL1>>>(
            Qh, Ql, DH_, TD, D_,
            Kh, Kl, DH_, TD, D_,
            S, nullptr, nullptr, (long)B_ * TT, TT, T_,
            nullptr, 0, 0, 0, cmax,
            B_, DH_, 0.125f, 0,
            nullptr, nullptr, nullptr, nullptr, nullptr, nullptr);
    }

    // 5) fused two-pass softmax + AV with qmask row-skip
    {
        dim3 g(T_ / 128, HB_);
        fsav_kernel<<<g, 256, FS_SMEM>>>(S, cmax, Vh, q1f, qmasks, R, Rh);
    }

    // 6) FFN1: hidden = relu(R @ fw1) -> fp16 (3-stage)
    {
        dim3 g(FF_ / 128, (B_ * T_) / 128, 1);
        mma4<false, false, 1, false, 3, false><<<g, 256, SM_PLAIN>>>(
            Rh, nullptr, 0, 0, D_, f1h, nullptr, 0, 0, FF_,
            nullptr, Hd, nullptr, 0, 0, FF_, nullptr, 0, 0, 0, nullptr, 1, D_, 1.f, 1,
            nullptr, nullptr, nullptr, nullptr, nullptr, nullptr);
    }

    // 7) FFN2: out = R + hidden @ fw2 -> fp32 (3-stage)
    {
        dim3 g(D_ / 128, (B_ * T_) / 128, 1);
        mma4<false, false, 0, false, 3, false><<<g, 256, SM_PLAIN>>>(
            Hd, nullptr, 0, 0, FF_, f2h, nullptr, 0, 0, D_,
            out, nullptr, nullptr, 0, 0, D_, R, 0, 0, D_, nullptr, 1, FF_, 1.f, 0,
            nullptr, nullptr, nullptr, nullptr, nullptr, nullptr);
    }
}

// round 13
// speedup vs baseline: 1.0449x; 1.0193x over previous
#include <cuda_runtime.h>
#include <cuda_fp16.h>
#include <math.h>
#include <stdint.h>

// Problem constants
constexpr int B_  = 32;
constexpr int T_  = 512;
constexpr int D_  = 512;
constexpr int H_  = 8;
constexpr int DH_ = 64;
constexpr int HB_ = H_ * B_;        // 256
constexpr int FF_ = 4 * D_;         // 2048

// ---------------- scratch (static device globals; allocation-free) ----------
__device__ float  g_pe [T_ * D_];
__device__ float  g_q1 [B_ * T_ * D_];              // fp32 residual
__device__ __half g_q1h[B_ * T_ * D_];
__device__ __half g_q1l[B_ * T_ * D_];
__device__ __half g_k1h[B_ * T_ * D_];
__device__ __half g_k1l[B_ * T_ * D_];
__device__ __half g_Qh [B_ * T_ * D_];
__device__ __half g_Ql [B_ * T_ * D_];
__device__ __half g_Kh [B_ * T_ * D_];
__device__ __half g_Kl [B_ * T_ * D_];
__device__ __half g_Vh [B_ * T_ * D_];
__device__ float  g_S  [(long)HB_ * T_ * T_];       // 256MB fp32 scores
__device__ float  g_cmax[HB_ * T_];
__device__ float  g_R  [B_ * T_ * D_];              // fp32 residual
__device__ __half g_Rh [B_ * T_ * D_];
__device__ __half g_H  [(long)B_ * T_ * FF_];       // hidden (fp16), 64MB
// converted weights
__device__ __half g_wqh[D_ * D_], g_wql[D_ * D_];
__device__ __half g_wkh[D_ * D_], g_wkl[D_ * D_];
__device__ __half g_wvh[D_ * D_];
__device__ __half g_f1h[D_ * FF_];
__device__ __half g_f2h[FF_ * D_];

// ---------------- helpers ---------------------------------------------------
__device__ __forceinline__ void mma16n8k16(float* c, const uint32_t* a, const uint32_t* b) {
    asm volatile(
        "mma.sync.aligned.m16n8k16.row.col.f32.f16.f16.f32 "
        "{%0,%1,%2,%3}, {%4,%5,%6,%7}, {%8,%9}, {%0,%1,%2,%3};"
        : "+f"(c[0]), "+f"(c[1]), "+f"(c[2]), "+f"(c[3])
        : "r"(a[0]), "r"(a[1]), "r"(a[2]), "r"(a[3]), "r"(b[0]), "r"(b[1]));
}
__device__ __forceinline__ void ldsm_x4(uint32_t* r, uint32_t a) {
    asm volatile("ldmatrix.sync.aligned.m8n8.x4.shared.b16 {%0,%1,%2,%3}, [%4];"
        : "=r"(r[0]), "=r"(r[1]), "=r"(r[2]), "=r"(r[3]) : "r"(a));
}
__device__ __forceinline__ void ldsm_x2(uint32_t* r, uint32_t a) {
    asm volatile("ldmatrix.sync.aligned.m8n8.x2.shared.b16 {%0,%1}, [%2];"
        : "=r"(r[0]), "=r"(r[1]) : "r"(a));
}
__device__ __forceinline__ void ldsm_x2t(uint32_t* r, uint32_t a) {
    asm volatile("ldmatrix.sync.aligned.m8n8.x2.trans.shared.b16 {%0,%1}, [%2];"
        : "=r"(r[0]), "=r"(r[1]) : "r"(a));
}
__device__ __forceinline__ uint32_t smem_u32(const void* p) {
    uint32_t a;
    asm("{ .reg .u64 t; cvta.to.shared.u64 t, %1; cvt.u32.u64 %0, t; }"
        : "=r"(a) : "l"(p));
    return a;
}
// cp.async with L1 bypass (.cg): keeps L1 bandwidth free for ldmatrix
__device__ __forceinline__ void cpa16(uint32_t saddr, const void* g) {
    asm volatile("cp.async.cg.shared.global [%0], [%1], 16;"
                 :: "r"(saddr), "l"(g) : "memory");
}
#define CPA_COMMIT() asm volatile("cp.async.commit_group;" ::: "memory")
#define CPA_WAIT1()  asm volatile("cp.async.wait_group 1;" ::: "memory")
#define CPA_WAIT0()  asm volatile("cp.async.wait_group 0;" ::: "memory")

__device__ __forceinline__ void atomicMaxFloat(float* addr, float v) {
    if (v >= 0.f) atomicMax((int*)addr, __float_as_int(v));
    else          atomicMin((unsigned int*)addr, __float_as_uint(v));
}

// ============ fp16 mma.sync GEMM engine v4 (ldmatrix + cp.async) ============
// Block tile 128x128, BK=32, 256 threads (8 warps: nWM=2, nWN=4; WM=64, WN=32).
// A row-major [M][K] fp16. B: TBB=0 -> [K][N]; TBB=1 -> [N][K].
// SPLIT: hi/lo planes, 3 MMAs. OUT: 0=fp32; 1=fp16 hi; 2=fp16 hi+lo.
// CM: fused column-max atomics. DUAL: blockIdx.z==1 selects alternate tensors.
// NS: pipeline depth (2 = preload-all fast path, requires K/BK <= 2; 3 = ring).
template<bool TBB, bool SPLIT, int OUT, bool CM, int NS, bool DUAL>
__global__ void __launch_bounds__(256, 2) mma4(
    const __half* __restrict__ Ah_g, const __half* __restrict__ Al_g,
    long sA1, long sA2, int lda,
    const __half* __restrict__ Bh_g, const __half* __restrict__ Bl_g,
    long sB1, long sB2, int ldb,
    float* Cf, __half* Chi, __half* Clo, long sC1, long sC2, int ldc,
    const float* __restrict__ Res, long sR1, long sR2, int ldres,
    float* cmaxp,
    int nb2, int K, float alpha, int relu,
    const __half* A2h, const __half* A2l,
    const __half* B2h, const __half* B2l,
    __half* C2hi, __half* C2lo)
{
    constexpr int BK  = 32;
    constexpr int AP  = 40;                 // A pitch (halves)
    constexpr int APL = 128 * AP;
    constexpr int NSP = SPLIT ? 2 : 1;
    constexpr int ASZ = NSP * APL;
    constexpr int BP  = 136;                // [K][N] B pitch
    constexpr int BPL = TBB ? APL : BK * BP;
    constexpr int BSZ = NSP * BPL;
    constexpr int STG = ASZ + BSZ;
    constexpr int MT  = 4;
    constexpr int NT  = 4;

    extern __shared__ __half smh[];
    const uint32_t sbase = smem_u32(smh);

    int z  = blockIdx.z;
    if (DUAL && z == 1) {
        Ah_g = A2h; Al_g = A2l; Bh_g = B2h; Bl_g = B2l;
        Chi = C2hi; Clo = C2lo;
    } else {
        int i1 = z / nb2, i2 = z % nb2;
        Ah_g += i1 * sA1 + i2 * sA2;
        if (SPLIT) Al_g += i1 * sA1 + i2 * sA2;
        Bh_g += i1 * sB1 + i2 * sB2;
        if (SPLIT) Bl_g += i1 * sB1 + i2 * sB2;
        if (OUT == 0) Cf  += i1 * sC1 + i2 * sC2;
        if (OUT >= 1) Chi += i1 * sC1 + i2 * sC2;
        if (OUT == 2) Clo += i1 * sC1 + i2 * sC2;
        if (Res) Res += i1 * sR1 + i2 * sR2;
        if (CM)  cmaxp += (long)z * ldc;
    }

    const int tid  = threadIdx.x;
    const int lane = tid & 31;
    const int wid  = tid >> 5;
    const int warp_m = wid & 1;
    const int warp_n = wid >> 1;
    const int row0 = blockIdx.y * 128;
    const int col0 = blockIdx.x * 128;
    const int frow = lane >> 2, fcol = lane & 3;

    float acc[MT][NT][4];
    #pragma unroll
    for (int i = 0; i < MT; i++)
        #pragma unroll
        for (int j = 0; j < NT; j++)
            #pragma unroll
            for (int q = 0; q < 4; q++) acc[i][j][q] = 0.f;

    auto load_stage = [&](int st, int k0) {
        uint32_t sA = sbase + (uint32_t)(st * STG) * 2;
        #pragma unroll
        for (int i = 0; i < 2 * NSP; i++) {
            int idx = i * 256 + tid;
            int plane = idx >> 9;
            int rem = idx & 511;
            int row = rem >> 2, c8 = (rem & 3) * 8;
            const __half* g = (SPLIT && plane ? Al_g : Ah_g)
                            + (long)(row0 + row) * lda + k0 + c8;
            cpa16(sA + (uint32_t)(plane * APL + row * AP + c8) * 2, g);
        }
        uint32_t sB = sbase + (uint32_t)(st * STG + ASZ) * 2;
        if (TBB) {
            #pragma unroll
            for (int i = 0; i < 2 * NSP; i++) {
                int idx = i * 256 + tid;
                int plane = idx >> 9;
                int rem = idx & 511;
                int row = rem >> 2, c8 = (rem & 3) * 8;
                const __half* g = (SPLIT && plane ? Bl_g : Bh_g)
                                + (long)(col0 + row) * ldb + k0 + c8;
                cpa16(sB + (uint32_t)(plane * APL + row * AP + c8) * 2, g);
            }
        } else {
            #pragma unroll
            for (int i = 0; i < 2 * NSP; i++) {
                int idx = i * 256 + tid;
                int plane = idx >> 9;
                int rem = idx & 511;
                int row = rem >> 4, c8 = (rem & 15) * 8;
                const __half* g = (SPLIT && plane ? Bl_g : Bh_g)
                                + (long)(k0 + row) * ldb + col0 + c8;
                cpa16(sB + (uint32_t)(plane * BPL + row * BP + c8) * 2, g);
            }
        }
    };

    auto compute = [&](int st) {
        const uint32_t aB = sbase + (uint32_t)(st * STG) * 2;
        const uint32_t bB = aB + (uint32_t)ASZ * 2;
        #pragma unroll
        for (int ks = 0; ks < 2; ks++) {
            const int kk = ks * 16;
            uint32_t af[MT][4], bh[NT][2];
            #pragma unroll
            for (int i = 0; i < MT; i++)
                ldsm_x4(af[i], aB + (uint32_t)((warp_m * 64 + i * 16 + (lane & 15)) * AP
                                               + kk + (lane >> 4) * 8) * 2);
            #pragma unroll
            for (int j = 0; j < NT; j++) {
                if (TBB)
                    ldsm_x2(bh[j], bB + (uint32_t)((warp_n * 32 + j * 8 + (lane & 7)) * AP
                                                   + kk + ((lane >> 3) & 1) * 8) * 2);
                else
                    ldsm_x2t(bh[j], bB + (uint32_t)((kk + (lane & 15)) * BP
                                                    + warp_n * 32 + j * 8) * 2);
            }
            #pragma unroll
            for (int i = 0; i < MT; i++)
                #pragma unroll
                for (int j = 0; j < NT; j++)
                    mma16n8k16(acc[i][j], af[i], bh[j]);
            if (SPLIT) {
                uint32_t b2[NT][2];
                #pragma unroll
                for (int j = 0; j < NT; j++) {
                    if (TBB)
                        ldsm_x2(b2[j], bB + (uint32_t)(APL + (warp_n * 32 + j * 8 + (lane & 7)) * AP
                                                       + kk + ((lane >> 3) & 1) * 8) * 2);
                    else
                        ldsm_x2t(b2[j], bB + (uint32_t)(BPL + (kk + (lane & 15)) * BP
                                                        + warp_n * 32 + j * 8) * 2);
                }
                #pragma unroll
                for (int i = 0; i < MT; i++)
                    #pragma unroll
                    for (int j = 0; j < NT; j++)
                        mma16n8k16(acc[i][j], af[i], b2[j]);
                #pragma unroll
                for (int i = 0; i < MT; i++)
                    ldsm_x4(af[i], aB + (uint32_t)(APL + (warp_m * 64 + i * 16 + (lane & 15)) * AP
                                                   + kk + (lane >> 4) * 8) * 2);
                #pragma unroll
                for (int i = 0; i < MT; i++)
                    #pragma unroll
                    for (int j = 0; j < NT; j++)
                        mma16n8k16(acc[i][j], af[i], bh[j]);
            }
        }
    };

    const int NTL = K / BK;
    if (NS == 3) {
        load_stage(0, 0);   CPA_COMMIT();
        load_stage(1, BK);  CPA_COMMIT();
        for (int kt = 0; kt < NTL; kt++) {
            CPA_WAIT1();
            __syncthreads();
            if (kt + 2 < NTL) load_stage((kt + 2) % 3, (kt + 2) * BK);
            CPA_COMMIT();
            compute(kt % 3);
        }
    } else {
        // NS == 2 fast path: K/BK <= 2 guaranteed by call sites.
        load_stage(0, 0);
        if (NTL > 1) load_stage(1, BK);
        CPA_COMMIT();
        CPA_WAIT0();
        __syncthreads();
        compute(0);
        if (NTL > 1) compute(1);
    }

    // ---- epilogue ----
    float colm[NT][2];
    if (CM) {
        #pragma unroll
        for (int j = 0; j < NT; j++) { colm[j][0] = -INFINITY; colm[j][1] = -INFINITY; }
    }
    #pragma unroll
    for (int i = 0; i < MT; i++) {
        #pragma unroll
        for (int j = 0; j < NT; j++) {
            int r = row0 + warp_m * 64 + i * 16 + frow;
            int c = col0 + warp_n * 32 + j * 8 + 2 * fcol;
            #pragma unroll
            for (int h = 0; h < 2; h++) {
                long rr = r + h * 8;
                float v0 = acc[i][j][2 * h] * alpha;
                float v1 = acc[i][j][2 * h + 1] * alpha;
                if (Res) {
                    v0 += Res[rr * (long)ldres + c];
                    v1 += Res[rr * (long)ldres + c + 1];
                }
                if (relu) { v0 = fmaxf(v0, 0.f); v1 = fmaxf(v1, 0.f); }
                if (CM) {
                    colm[j][0] = fmaxf(colm[j][0], v0);
                    colm[j][1] = fmaxf(colm[j][1], v1);
                }
                if (OUT == 0)
                    *(float2*)&Cf[rr * (long)ldc + c] = make_float2(v0, v1);
                if (OUT >= 1) {
                    __half h0 = __float2half_rn(v0), h1 = __float2half_rn(v1);
                    *(__half2*)&Chi[rr * (long)ldc + c] = __halves2half2(h0, h1);
                    if (OUT == 2) {
                        __half l0 = __float2half_rn(v0 - __half2float(h0));
                        __half l1 = __float2half_rn(v1 - __half2float(h1));
                        *(__half2*)&Clo[rr * (long)ldc + c] = __halves2half2(l0, l1);
                    }
                }
            }
        }
    }
    if (CM) {
        #pragma unroll
        for (int j = 0; j < NT; j++) {
            #pragma unroll
            for (int s = 4; s <= 16; s <<= 1) {
                colm[j][0] = fmaxf(colm[j][0], __shfl_xor_sync(0xffffffffu, colm[j][0], s));
                colm[j][1] = fmaxf(colm[j][1], __shfl_xor_sync(0xffffffffu, colm[j][1], s));
            }
        }
        if (frow == 0) {
            #pragma unroll
            for (int j = 0; j < NT; j++) {
                int c = col0 + warp_n * 32 + j * 8 + 2 * fcol;
                atomicMaxFloat(&cmaxp[c],     colm[j][0]);
                atomicMaxFloat(&cmaxp[c + 1], colm[j][1]);
            }
        }
    }
}

constexpr int smem4(bool TBB, bool SPLIT, int NS) {
    int APL = 128 * 40, NSP = SPLIT ? 2 : 1;
    int BPL = TBB ? APL : 32 * 136;
    return 2 * NS * NSP * (APL + BPL);
}

// ============ fused two-pass softmax + AV (fp16 MMA), qmask skipping ========
// grid (T/128, HB), 256 threads. p tile [128][72] halves; V tile [64][72].
// Row-level skip: rows q >= qmasks[b] are zeroed by the qmask after softmax.
// Tile-level skip: blocks with q0 >= qmasks[b] output pure residual.
constexpr int FS_PB   = 0;
constexpr int FS_VB   = FS_PB + 2 * 128 * 72 * 2;      // 36864
constexpr int FS_CM   = FS_VB + 2 * 64 * 72 * 2;       // 55296
constexpr int FS_MM   = FS_CM + 512 * 4;               // 57344
constexpr int FS_SS   = FS_MM + 128 * 4;               // 57856
constexpr int FS_SMEM = FS_SS + 128 * 4;               // 58368

__global__ __launch_bounds__(256, 2) void fsav_kernel(
    const float* __restrict__ S,
    const float* __restrict__ cmax,
    const __half* __restrict__ Vh,
    const float* __restrict__ q1f,
    const int* __restrict__ qmasks,
    float* __restrict__ Rf, __half* __restrict__ Rh)
{
    extern __shared__ char fs[];
    float* cm  = (float*)(fs + FS_CM);
    float* smM = (float*)(fs + FS_MM);
    float* smS = (float*)(fs + FS_SS);
    const uint32_t sbase = smem_u32(fs);

    const int tid = threadIdx.x, lane = tid & 31, wid = tid >> 5;
    const int q0 = blockIdx.x * 128;
    const int z  = blockIdx.y;
    const int hh = z / B_, b = z % B_;
    const float*  Sz = S + (long)z * T_ * T_;
    const __half* Vz = Vh + (long)b * T_ * D_ + hh * DH_;
    const float*  Qz = q1f + (long)b * T_ * D_ + hh * DH_;
    float*  Rfz = Rf + (long)b * T_ * D_ + hh * DH_;
    __half* Rhz = Rh + (long)b * T_ * D_ + hh * DH_;
    const int qlim = qmasks[b];

    // ---- tile-level early exit: whole q-tile masked -> R = q1 residual ----
    if (q0 >= qlim) {
        // 128 rows x 64 cols (this head's slice) = 4096 float2 chunks
        #pragma unroll
        for (int i = 0; i < 16; i++) {
            int idx = i * 256 + tid;
            int r = idx >> 5;                 // 0..127
            int c2 = (idx & 31) * 2;          // 0..62
            long off = (long)(q0 + r) * D_ + c2;
            float2 v = *(const float2*)&Qz[off];
            *(float2*)&Rfz[off] = v;
            *(__half2*)&Rhz[off] = __floats2half2_rn(v.x, v.y);
        }
        return;
    }

    cm[tid]       = cmax[z * T_ + tid];
    cm[tid + 256] = cmax[z * T_ + tid + 256];
    __syncthreads();

    // ---- phase 1: per-row max & sum (one warp per row); skip masked rows ----
    for (int it = 0; it < 16; it++) {
        int r = it * 8 + wid;
        if (q0 + r >= qlim) {
            if (lane == 0) { smM[r] = 0.f; smS[r] = 1.f; }  // benign (row zeroed)
            continue;
        }
        const float* Srow = Sz + (long)(q0 + r) * T_;
        float x[16];
        #pragma unroll
        for (int seg = 0; seg < 4; seg++) {
            float4 v = *(const float4*)(Srow + seg * 128 + lane * 4);
            int c = seg * 128 + lane * 4;
            x[seg * 4 + 0] = v.x - cm[c + 0];
            x[seg * 4 + 1] = v.y - cm[c + 1];
            x[seg * 4 + 2] = v.z - cm[c + 2];
            x[seg * 4 + 3] = v.w - cm[c + 3];
        }
        float m = x[0];
        #pragma unroll
        for (int j = 1; j < 16; j++) m = fmaxf(m, x[j]);
        #pragma unroll
        for (int o = 16; o; o >>= 1) m = fmaxf(m, __shfl_xor_sync(0xffffffffu, m, o));
        float s = 0.f;
        #pragma unroll
        for (int j = 0; j < 16; j++) s += expf(x[j] - m);
        #pragma unroll
        for (int o = 16; o; o >>= 1) s += __shfl_xor_sync(0xffffffffu, s, o);
        if (lane == 0) { smM[r] = m; smS[r] = s; }
    }
    __syncthreads();

    // ---- phase 2: stream k-tiles of 64: regenerate p (fp16), MMA with V ----
    const int warp_m = wid & 3, warp_n = wid >> 2;  // WM=32 (MT=2), WN=32 (NT=4)
    const int frow = lane >> 2, fcol = lane & 3;

    float acc[2][4][4];
    #pragma unroll
    for (int i = 0; i < 2; i++)
        #pragma unroll
        for (int j = 0; j < 4; j++)
            #pragma unroll
            for (int q = 0; q < 4; q++) acc[i][j][q] = 0.f;

    auto loadV = [&](int buf, int k0) {
        #pragma unroll
        for (int i = 0; i < 2; i++) {
            int idx = i * 256 + tid;
            int row = idx >> 3, c8 = (idx & 7) * 8;
            cpa16(sbase + (uint32_t)(FS_VB + (buf * 64 * 72 + row * 72 + c8) * 2),
                  Vz + (long)(k0 + row) * D_ + c8);
        }
    };
    auto genP = [&](int buf, int k0) {
        __half* pt = (__half*)(fs + FS_PB) + buf * 128 * 72;
        #pragma unroll
        for (int pass = 0; pass < 8; pass++) {
            int r = pass * 16 + (tid >> 4);
            int c4 = (tid & 15) * 4;
            if (q0 + r >= qlim) {
                *(__half2*)&pt[r * 72 + c4]     = __halves2half2(__ushort_as_half(0),
                                                                 __ushort_as_half(0));
                *(__half2*)&pt[r * 72 + c4 + 2] = __halves2half2(__ushort_as_half(0),
                                                                 __ushort_as_half(0));
                continue;
            }
            float4 v = *(const float4*)(Sz + (long)(q0 + r) * T_ + k0 + c4);
            float mm = smM[r];
            __half2 p0 = __floats2half2_rn(expf(v.x - cm[k0 + c4 + 0] - mm),
                                           expf(v.y - cm[k0 + c4 + 1] - mm));
            __half2 p1 = __floats2half2_rn(expf(v.z - cm[k0 + c4 + 2] - mm),
                                           expf(v.w - cm[k0 + c4 + 3] - mm));
            *(__half2*)&pt[r * 72 + c4]     = p0;
            *(__half2*)&pt[r * 72 + c4 + 2] = p1;
        }
    };

    loadV(0, 0); CPA_COMMIT();

    for (int kt = 0; kt < 8; kt++) {
        int buf = kt & 1;
        genP(buf, kt * 64);
        CPA_WAIT0();
        __syncthreads();
        if (kt + 1 < 8) { loadV(buf ^ 1, (kt + 1) * 64); CPA_COMMIT(); }
        const uint32_t pB = sbase + (uint32_t)(FS_PB + buf * 128 * 72 * 2);
        const uint32_t vB = sbase + (uint32_t)(FS_VB + buf * 64 * 72 * 2);
        #pragma unroll
        for (int ks = 0; ks < 4; ks++) {
            const int kk = ks * 16;
            uint32_t af[2][4], bf[4][2];
            #pragma unroll
            for (int i = 0; i < 2; i++)
                ldsm_x4(af[i], pB + (uint32_t)((warp_m * 32 + i * 16 + (lane & 15)) * 72
                                               + kk + (lane >> 4) * 8) * 2);
            #pragma unroll
            for (int j = 0; j < 4; j++)
                ldsm_x2t(bf[j], vB + (uint32_t)((kk + (lane & 15)) * 72
                                                + warp_n * 32 + j * 8) * 2);
            #pragma unroll
            for (int i = 0; i < 2; i++)
                #pragma unroll
                for (int j = 0; j < 4; j++)
                    mma16n8k16(acc[i][j], af[i], bf[j]);
        }
        __syncthreads();
    }

    // ---- epilogue: scale by qmask/sum, add residual, write fp32 + fp16 ----
    #pragma unroll
    for (int i = 0; i < 2; i++) {
        #pragma unroll
        for (int j = 0; j < 4; j++) {
            int rloc = warp_m * 32 + i * 16 + frow;
            int c = warp_n * 32 + j * 8 + 2 * fcol;
            #pragma unroll
            for (int h = 0; h < 2; h++) {
                int rr = rloc + h * 8;
                float inv = ((q0 + rr) < qlim ? 1.f : 0.f) / smS[rr];
                long off = (long)(q0 + rr) * D_ + c;
                float v0 = acc[i][j][2 * h] * inv + Qz[off];
                float v1 = acc[i][j][2 * h + 1] * inv + Qz[off + 1];
                *(float2*)&Rfz[off] = make_float2(v0, v1);
                *(__half2*)&Rhz[off] = __floats2half2_rn(v0, v1);
            }
        }
    }
}

// ---------------- positional encoding (fp64 to match numpy) -----------------
__global__ void pe_kernel(float* __restrict__ pe) {
    int idx = blockIdx.x * blockDim.x + threadIdx.x;
    if (idx >= T_ * D_) return;
    int t = idx / D_;
    int d = idx % D_;
    double ang = (double)t * exp(-(2.0 * (double)d / (double)D_) * log(10000.0));
    double v = (d & 1) ? cos(ang) : sin(ang);
    pe[idx] = (float)(v * sqrt((double)D_));
}

__global__ void addpe2_kernel(const float* __restrict__ q, const float* __restrict__ pe,
                              float* __restrict__ q1f,
                              __half* __restrict__ q1h, __half* __restrict__ q1l,
                              __half* __restrict__ k1h, __half* __restrict__ k1l) {
    long idx = (long)blockIdx.x * blockDim.x + threadIdx.x;
    long td = idx % ((long)T_ * D_);
    float p = pe[td];
    float a = q[idx] + p;
    q1f[idx] = a;
    __half ah = __float2half_rn(a);
    q1h[idx] = ah;
    q1l[idx] = __float2half_rn(a - __half2float(ah));
    float bb = a + p;                      // k1 = q1 + pe (source bug kept)
    __half bh = __float2half_rn(bb);
    k1h[idx] = bh;
    k1l[idx] = __float2half_rn(bb - __half2float(bh));
}

// single fused conversion kernel: all weights + cmax init
__global__ void cvt_all_kernel(const float* __restrict__ wq, const float* __restrict__ wk,
                               const float* __restrict__ wv, const float* __restrict__ f1,
                               const float* __restrict__ f2,
                               __half* __restrict__ wqh, __half* __restrict__ wql,
                               __half* __restrict__ wkh, __half* __restrict__ wkl,
                               __half* __restrict__ wvh,
                               __half* __restrict__ f1h, __half* __restrict__ f2h,
                               float* __restrict__ cmaxp) {
    constexpr int DD = D_ * D_;
    constexpr int DF = D_ * FF_;
    int i = blockIdx.x * blockDim.x + threadIdx.x;
    if (i < DD) {
        float x = wq[i];
        __half h = __float2half_rn(x);
        wqh[i] = h;
        wql[i] = __float2half_rn(x - __half2float(h));
    } else if (i < 2 * DD) {
        int j = i - DD;
        float x = wk[j];
        __half h = __float2half_rn(x);
        wkh[j] = h;
        wkl[j] = __float2half_rn(x - __half2float(h));
    } else if (i < 3 * DD) {
        int j = i - 2 * DD;
        wvh[j] = __float2half_rn(wv[j]);
    } else if (i < 3 * DD + DF) {
        int j = i - 3 * DD;
        f1h[j] = __float2half_rn(f1[j]);
    } else if (i < 3 * DD + 2 * DF) {
        int j = i - 3 * DD - DF;
        f2h[j] = __float2half_rn(f2[j]);
    } else if (i < 3 * DD + 2 * DF + HB_ * T_) {
        cmaxp[i - 3 * DD - 2 * DF] = -INFINITY;
    }
}

// ---------------- launch -----------------------------------------------------
extern "C" void kernel_launch(void* const* d_in, const int* in_sizes, int n_in,
                              void* d_out, int out_size) {
    const float* queries = (const float*)d_in[0];
    const int*   qmasks  = (const int*)d_in[2];
    const float* W_Q = (const float*)d_in[4];
    const float* W_K = (const float*)d_in[5];
    const float* W_V = (const float*)d_in[6];
    const float* fw1 = (const float*)d_in[7];
    const float* fw2 = (const float*)d_in[8];
    float* out = (float*)d_out;

    float *pe, *q1f, *S, *cmax, *R;
    __half *q1h, *q1l, *k1h, *k1l, *Qh, *Ql, *Kh, *Kl, *Vh, *Rh, *Hd;
    __half *wqh, *wql, *wkh, *wkl, *wvh, *f1h, *f2h;
    cudaGetSymbolAddress((void**)&pe,  g_pe);
    cudaGetSymbolAddress((void**)&q1f, g_q1);
    cudaGetSymbolAddress((void**)&q1h, g_q1h);
    cudaGetSymbolAddress((void**)&q1l, g_q1l);
    cudaGetSymbolAddress((void**)&k1h, g_k1h);
    cudaGetSymbolAddress((void**)&k1l, g_k1l);
    cudaGetSymbolAddress((void**)&Qh,  g_Qh);
    cudaGetSymbolAddress((void**)&Ql,  g_Ql);
    cudaGetSymbolAddress((void**)&Kh,  g_Kh);
    cudaGetSymbolAddress((void**)&Kl,  g_Kl);
    cudaGetSymbolAddress((void**)&Vh,  g_Vh);
    cudaGetSymbolAddress((void**)&S,   g_S);
    cudaGetSymbolAddress((void**)&cmax, g_cmax);
    cudaGetSymbolAddress((void**)&R,   g_R);
    cudaGetSymbolAddress((void**)&Rh,  g_Rh);
    cudaGetSymbolAddress((void**)&Hd,  g_H);
    cudaGetSymbolAddress((void**)&wqh, g_wqh);
    cudaGetSymbolAddress((void**)&wql, g_wql);
    cudaGetSymbolAddress((void**)&wkh, g_wkh);
    cudaGetSymbolAddress((void**)&wkl, g_wkl);
    cudaGetSymbolAddress((void**)&wvh, g_wvh);
    cudaGetSymbolAddress((void**)&f1h, g_f1h);
    cudaGetSymbolAddress((void**)&f2h, g_f2h);

    const long TD = (long)T_ * D_;
    const long TT = (long)T_ * T_;

    constexpr int SM_PLAIN = smem4(false, false, 3);  // 56832
    constexpr int SM_SPL3  = smem4(false, true,  3);  // 113664 (2 CTAs: 227328)
    constexpr int SM_SPL1  = smem4(true,  true,  2);  // 81920

    cudaFuncSetAttribute((const void*)mma4<false, true,  2, false, 3, true>,
                         cudaFuncAttributeMaxDynamicSharedMemorySize, SM_SPL3);
    cudaFuncSetAttribute((const void*)mma4<true,  true,  0, true,  2, false>,
                         cudaFuncAttributeMaxDynamicSharedMemorySize, SM_SPL1);
    cudaFuncSetAttribute((const void*)mma4<false, false, 1, false, 3, false>,
                         cudaFuncAttributeMaxDynamicSharedMemorySize, SM_PLAIN);
    cudaFuncSetAttribute((const void*)mma4<false, false, 0, false, 3, false>,
                         cudaFuncAttributeMaxDynamicSharedMemorySize, SM_PLAIN);
    cudaFuncSetAttribute((const void*)fsav_kernel,
                         cudaFuncAttributeMaxDynamicSharedMemorySize, FS_SMEM);

    // 1) posenc + all conversions (+cmax init)
    pe_kernel<<<(T_ * D_ + 255) / 256, 256>>>(pe);
    addpe2_kernel<<<(B_ * T_ * D_) / 256, 256>>>(queries, pe, q1f, q1h, q1l, k1h, k1l);
    {
        int n = 3 * D_ * D_ + 2 * D_ * FF_ + HB_ * T_;
        cvt_all_kernel<<<(n + 255) / 256, 256>>>(W_Q, W_K, W_V, fw1, fw2,
                                                 wqh, wql, wkh, wkl, wvh, f1h, f2h, cmax);
    }

    // 2) Q and K projections batched in one DUAL launch (fp16 split, 3-stage)
    {
        dim3 g(D_ / 128, (B_ * T_) / 128, 2);
        mma4<false, true, 2, false, 3, true><<<g, 256, SM_SPL3>>>(
            q1h, q1l, 0, 0, D_, wqh, wql, 0, 0, D_,
            nullptr, Qh, Ql, 0, 0, D_, nullptr, 0, 0, 0, nullptr, 1, D_, 1.f, 0,
            k1h, k1l, wkh, wkl, Kh, Kl);
    }

    // 3) V projection: V = Kp @ W_V (bug kept) -> fp16 (3-stage)
    {
        dim3 g(D_ / 128, (B_ * T_) / 128, 1);
        mma4<false, false, 1, false, 3, false><<<g, 256, SM_PLAIN>>>(
            Kh, nullptr, 0, 0, D_, wvh, nullptr, 0, 0, D_,
            nullptr, Vh, nullptr, 0, 0, D_, nullptr, 0, 0, 0, nullptr, 1, D_, 1.f, 0,
            nullptr, nullptr, nullptr, nullptr, nullptr, nullptr);
    }

    // 4) scores (fp16 split, B=[N][K]) -> fp32 S + fused column-max atomics
    //    K=64 -> NTL=2 -> NS=2 preload-all fast path
    {
        dim3 g(T_ / 128, T_ / 128, HB_);
        mma4<true, true, 0, true, 2, false><<<g, 256, SM_SPL1>>>(
            Qh, Ql, DH_, TD, D_,
            Kh, Kl, DH_, TD, D_,
            S, nullptr, nullptr, (long)B_ * TT, TT, T_,
            nullptr, 0, 0, 0, cmax,
            B_, DH_, 0.125f, 0,
            nullptr, nullptr, nullptr, nullptr, nullptr, nullptr);
    }

    // 5) fused two-pass softmax + AV with qmask row- and tile-skip
    {
        dim3 g(T_ / 128, HB_);
        fsav_kernel<<<g, 256, FS_SMEM>>>(S, cmax, Vh, q1f, qmasks, R, Rh);
    }

    // 6) FFN1: hidden = relu(R @ fw1) -> fp16 (3-stage)
    {
        dim3 g(FF_ / 128, (B_ * T_) / 128, 1);
        mma4<false, false, 1, false, 3, false><<<g, 256, SM_PLAIN>>>(
            Rh, nullptr, 0, 0, D_, f1h, nullptr, 0, 0, FF_,
            nullptr, Hd, nullptr, 0, 0, FF_, nullptr, 0, 0, 0, nullptr, 1, D_, 1.f, 1,
            nullptr, nullptr, nullptr, nullptr, nullptr, nullptr);
    }

    // 7) FFN2: out = R + hidden @ fw2 -> fp32 (3-stage)
    {
        dim3 g(D_ / 128, (B_ * T_) / 128, 1);
        mma4<false, false, 0, false, 3, false><<<g, 256, SM_PLAIN>>>(
            Hd, nullptr, 0, 0, FF_, f2h, nullptr, 0, 0, D_,
            out, nullptr, nullptr, 0, 0, D_, R, 0, 0, D_, nullptr, 1, FF_, 1.f, 0,
            nullptr, nullptr, nullptr, nullptr, nullptr, nullptr);
    }
}

// round 14
// speedup vs baseline: 1.0728x; 1.0267x over previous
#include <cuda_runtime.h>
#include <cuda_fp16.h>
#include <math.h>
#include <stdint.h>

// Problem constants
constexpr int B_  = 32;
constexpr int T_  = 512;
constexpr int D_  = 512;
constexpr int H_  = 8;
constexpr int DH_ = 64;
constexpr int HB_ = H_ * B_;        // 256
constexpr int FF_ = 4 * D_;         // 2048

// ---------------- scratch (static device globals; allocation-free) ----------
__device__ float  g_pe [T_ * D_];
__device__ float  g_q1 [B_ * T_ * D_];              // fp32 residual
__device__ __half g_q1h[B_ * T_ * D_];
__device__ __half g_q1l[B_ * T_ * D_];
__device__ __half g_k1h[B_ * T_ * D_];
__device__ __half g_k1l[B_ * T_ * D_];
__device__ __half g_Qh [B_ * T_ * D_];
__device__ __half g_Ql [B_ * T_ * D_];
__device__ __half g_Kh [B_ * T_ * D_];
__device__ __half g_Kl [B_ * T_ * D_];
__device__ __half g_Vh [B_ * T_ * D_];
__device__ float  g_S  [(long)HB_ * T_ * T_];       // 256MB fp32 scores
__device__ float  g_cmax[HB_ * T_];
__device__ float  g_R  [B_ * T_ * D_];              // fp32 residual
__device__ __half g_Rh [B_ * T_ * D_];
__device__ __half g_H  [(long)B_ * T_ * FF_];       // hidden (fp16), 64MB
// converted weights
__device__ __half g_wqh[D_ * D_], g_wql[D_ * D_];
__device__ __half g_wkh[D_ * D_], g_wkl[D_ * D_];
__device__ __half g_wvh[D_ * D_];
__device__ __half g_f1h[D_ * FF_];
__device__ __half g_f2h[FF_ * D_];

// ---------------- helpers ---------------------------------------------------
__device__ __forceinline__ void mma16n8k16(float* c, const uint32_t* a, const uint32_t* b) {
    asm volatile(
        "mma.sync.aligned.m16n8k16.row.col.f32.f16.f16.f32 "
        "{%0,%1,%2,%3}, {%4,%5,%6,%7}, {%8,%9}, {%0,%1,%2,%3};"
        : "+f"(c[0]), "+f"(c[1]), "+f"(c[2]), "+f"(c[3])
        : "r"(a[0]), "r"(a[1]), "r"(a[2]), "r"(a[3]), "r"(b[0]), "r"(b[1]));
}
__device__ __forceinline__ void ldsm_x4(uint32_t* r, uint32_t a) {
    asm volatile("ldmatrix.sync.aligned.m8n8.x4.shared.b16 {%0,%1,%2,%3}, [%4];"
        : "=r"(r[0]), "=r"(r[1]), "=r"(r[2]), "=r"(r[3]) : "r"(a));
}
__device__ __forceinline__ void ldsm_x2(uint32_t* r, uint32_t a) {
    asm volatile("ldmatrix.sync.aligned.m8n8.x2.shared.b16 {%0,%1}, [%2];"
        : "=r"(r[0]), "=r"(r[1]) : "r"(a));
}
__device__ __forceinline__ void ldsm_x2t(uint32_t* r, uint32_t a) {
    asm volatile("ldmatrix.sync.aligned.m8n8.x2.trans.shared.b16 {%0,%1}, [%2];"
        : "=r"(r[0]), "=r"(r[1]) : "r"(a));
}
__device__ __forceinline__ uint32_t smem_u32(const void* p) {
    uint32_t a;
    asm("{ .reg .u64 t; cvta.to.shared.u64 t, %1; cvt.u32.u64 %0, t; }"
        : "=r"(a) : "l"(p));
    return a;
}
// cp.async with L1 bypass (.cg): keeps L1 bandwidth free for ldmatrix
__device__ __forceinline__ void cpa16(uint32_t saddr, const void* g) {
    asm volatile("cp.async.cg.shared.global [%0], [%1], 16;"
                 :: "r"(saddr), "l"(g) : "memory");
}
#define CPA_COMMIT() asm volatile("cp.async.commit_group;" ::: "memory")
#define CPA_WAIT1()  asm volatile("cp.async.wait_group 1;" ::: "memory")
#define CPA_WAIT0()  asm volatile("cp.async.wait_group 0;" ::: "memory")

__device__ __forceinline__ void atomicMaxFloat(float* addr, float v) {
    if (v >= 0.f) atomicMax((int*)addr, __float_as_int(v));
    else          atomicMin((unsigned int*)addr, __float_as_uint(v));
}

// ============ fp16 mma.sync GEMM engine v4 (ldmatrix + cp.async) ============
// Block tile 128x128, BK=32, 256 threads (8 warps: nWM=2, nWN=4; WM=64, WN=32).
// A row-major [M][K] fp16. B: TBB=0 -> [K][N]; TBB=1 -> [N][K].
// SPLIT: hi/lo planes, 3 MMAs. OUT: 0=fp32; 1=fp16 hi; 2=fp16 hi+lo.
// CM: fused column-max atomics; with qm_p set, rows rr >= qm_p[i2] are not
//     stored to C (they only feed the colmax; consumer never reads them).
// DUAL: blockIdx.z==1 selects alternate tensors.
// NS: pipeline depth (2 = preload-all fast path, requires K/BK <= 2; 3 = ring).
template<bool TBB, bool SPLIT, int OUT, bool CM, int NS, bool DUAL>
__global__ void __launch_bounds__(256, 2) mma4(
    const __half* __restrict__ Ah_g, const __half* __restrict__ Al_g,
    long sA1, long sA2, int lda,
    const __half* __restrict__ Bh_g, const __half* __restrict__ Bl_g,
    long sB1, long sB2, int ldb,
    float* Cf, __half* Chi, __half* Clo, long sC1, long sC2, int ldc,
    const float* __restrict__ Res, long sR1, long sR2, int ldres,
    float* cmaxp, const int* __restrict__ qm_p,
    int nb2, int K, float alpha, int relu,
    const __half* A2h, const __half* A2l,
    const __half* B2h, const __half* B2l,
    __half* C2hi, __half* C2lo)
{
    constexpr int BK  = 32;
    constexpr int AP  = 40;                 // A pitch (halves)
    constexpr int APL = 128 * AP;
    constexpr int NSP = SPLIT ? 2 : 1;
    constexpr int ASZ = NSP * APL;
    constexpr int BP  = 136;                // [K][N] B pitch
    constexpr int BPL = TBB ? APL : BK * BP;
    constexpr int BSZ = NSP * BPL;
    constexpr int STG = ASZ + BSZ;
    constexpr int MT  = 4;
    constexpr int NT  = 4;

    extern __shared__ __half smh[];
    const uint32_t sbase = smem_u32(smh);

    int z  = blockIdx.z;
    int qlim = 1 << 30;                      // default: store all rows
    if (DUAL && z == 1) {
        Ah_g = A2h; Al_g = A2l; Bh_g = B2h; Bl_g = B2l;
        Chi = C2hi; Clo = C2lo;
    } else {
        int i1 = z / nb2, i2 = z % nb2;
        Ah_g += i1 * sA1 + i2 * sA2;
        if (SPLIT) Al_g += i1 * sA1 + i2 * sA2;
        Bh_g += i1 * sB1 + i2 * sB2;
        if (SPLIT) Bl_g += i1 * sB1 + i2 * sB2;
        if (OUT == 0) Cf  += i1 * sC1 + i2 * sC2;
        if (OUT >= 1) Chi += i1 * sC1 + i2 * sC2;
        if (OUT == 2) Clo += i1 * sC1 + i2 * sC2;
        if (Res) Res += i1 * sR1 + i2 * sR2;
        if (CM) {
            cmaxp += (long)z * ldc;
            if (qm_p) qlim = qm_p[i2];       // scores: i2 = batch index
        }
    }

    const int tid  = threadIdx.x;
    const int lane = tid & 31;
    const int wid  = tid >> 5;
    const int warp_m = wid & 1;
    const int warp_n = wid >> 1;
    const int row0 = blockIdx.y * 128;
    const int col0 = blockIdx.x * 128;
    const int frow = lane >> 2, fcol = lane & 3;

    float acc[MT][NT][4];
    #pragma unroll
    for (int i = 0; i < MT; i++)
        #pragma unroll
        for (int j = 0; j < NT; j++)
            #pragma unroll
            for (int q = 0; q < 4; q++) acc[i][j][q] = 0.f;

    auto load_stage = [&](int st, int k0) {
        uint32_t sA = sbase + (uint32_t)(st * STG) * 2;
        #pragma unroll
        for (int i = 0; i < 2 * NSP; i++) {
            int idx = i * 256 + tid;
            int plane = idx >> 9;
            int rem = idx & 511;
            int row = rem >> 2, c8 = (rem & 3) * 8;
            const __half* g = (SPLIT && plane ? Al_g : Ah_g)
                            + (long)(row0 + row) * lda + k0 + c8;
            cpa16(sA + (uint32_t)(plane * APL + row * AP + c8) * 2, g);
        }
        uint32_t sB = sbase + (uint32_t)(st * STG + ASZ) * 2;
        if (TBB) {
            #pragma unroll
            for (int i = 0; i < 2 * NSP; i++) {
                int idx = i * 256 + tid;
                int plane = idx >> 9;
                int rem = idx & 511;
                int row = rem >> 2, c8 = (rem & 3) * 8;
                const __half* g = (SPLIT && plane ? Bl_g : Bh_g)
                                + (long)(col0 + row) * ldb + k0 + c8;
                cpa16(sB + (uint32_t)(plane * APL + row * AP + c8) * 2, g);
            }
        } else {
            #pragma unroll
            for (int i = 0; i < 2 * NSP; i++) {
                int idx = i * 256 + tid;
                int plane = idx >> 9;
                int rem = idx & 511;
                int row = rem >> 4, c8 = (rem & 15) * 8;
                const __half* g = (SPLIT && plane ? Bl_g : Bh_g)
                                + (long)(k0 + row) * ldb + col0 + c8;
                cpa16(sB + (uint32_t)(plane * BPL + row * BP + c8) * 2, g);
            }
        }
    };

    auto compute = [&](int st) {
        const uint32_t aB = sbase + (uint32_t)(st * STG) * 2;
        const uint32_t bB = aB + (uint32_t)ASZ * 2;
        #pragma unroll
        for (int ks = 0; ks < 2; ks++) {
            const int kk = ks * 16;
            uint32_t af[MT][4], bh[NT][2];
            #pragma unroll
            for (int i = 0; i < MT; i++)
                ldsm_x4(af[i], aB + (uint32_t)((warp_m * 64 + i * 16 + (lane & 15)) * AP
                                               + kk + (lane >> 4) * 8) * 2);
            #pragma unroll
            for (int j = 0; j < NT; j++) {
                if (TBB)
                    ldsm_x2(bh[j], bB + (uint32_t)((warp_n * 32 + j * 8 + (lane & 7)) * AP
                                                   + kk + ((lane >> 3) & 1) * 8) * 2);
                else
                    ldsm_x2t(bh[j], bB + (uint32_t)((kk + (lane & 15)) * BP
                                                    + warp_n * 32 + j * 8) * 2);
            }
            #pragma unroll
            for (int i = 0; i < MT; i++)
                #pragma unroll
                for (int j = 0; j < NT; j++)
                    mma16n8k16(acc[i][j], af[i], bh[j]);
            if (SPLIT) {
                uint32_t b2[NT][2];
                #pragma unroll
                for (int j = 0; j < NT; j++) {
                    if (TBB)
                        ldsm_x2(b2[j], bB + (uint32_t)(APL + (warp_n * 32 + j * 8 + (lane & 7)) * AP
                                                       + kk + ((lane >> 3) & 1) * 8) * 2);
                    else
                        ldsm_x2t(b2[j], bB + (uint32_t)(BPL + (kk + (lane & 15)) * BP
                                                        + warp_n * 32 + j * 8) * 2);
                }
                #pragma unroll
                for (int i = 0; i < MT; i++)
                    #pragma unroll
                    for (int j = 0; j < NT; j++)
                        mma16n8k16(acc[i][j], af[i], b2[j]);
                #pragma unroll
                for (int i = 0; i < MT; i++)
                    ldsm_x4(af[i], aB + (uint32_t)(APL + (warp_m * 64 + i * 16 + (lane & 15)) * AP
                                                   + kk + (lane >> 4) * 8) * 2);
                #pragma unroll
                for (int i = 0; i < MT; i++)
                    #pragma unroll
                    for (int j = 0; j < NT; j++)
                        mma16n8k16(acc[i][j], af[i], bh[j]);
            }
        }
    };

    const int NTL = K / BK;
    if (NS == 3) {
        load_stage(0, 0);   CPA_COMMIT();
        load_stage(1, BK);  CPA_COMMIT();
        for (int kt = 0; kt < NTL; kt++) {
            CPA_WAIT1();
            __syncthreads();
            if (kt + 2 < NTL) load_stage((kt + 2) % 3, (kt + 2) * BK);
            CPA_COMMIT();
            compute(kt % 3);
        }
    } else {
        // NS == 2 fast path: K/BK <= 2 guaranteed by call sites.
        load_stage(0, 0);
        if (NTL > 1) load_stage(1, BK);
        CPA_COMMIT();
        CPA_WAIT0();
        __syncthreads();
        compute(0);
        if (NTL > 1) compute(1);
    }

    // ---- epilogue ----
    float colm[NT][2];
    if (CM) {
        #pragma unroll
        for (int j = 0; j < NT; j++) { colm[j][0] = -INFINITY; colm[j][1] = -INFINITY; }
    }
    #pragma unroll
    for (int i = 0; i < MT; i++) {
        #pragma unroll
        for (int j = 0; j < NT; j++) {
            int r = row0 + warp_m * 64 + i * 16 + frow;
            int c = col0 + warp_n * 32 + j * 8 + 2 * fcol;
            #pragma unroll
            for (int h = 0; h < 2; h++) {
                long rr = r + h * 8;
                float v0 = acc[i][j][2 * h] * alpha;
                float v1 = acc[i][j][2 * h + 1] * alpha;
                if (Res) {
                    v0 += Res[rr * (long)ldres + c];
                    v1 += Res[rr * (long)ldres + c + 1];
                }
                if (relu) { v0 = fmaxf(v0, 0.f); v1 = fmaxf(v1, 0.f); }
                if (CM) {
                    colm[j][0] = fmaxf(colm[j][0], v0);
                    colm[j][1] = fmaxf(colm[j][1], v1);
                }
                if (OUT == 0) {
                    // CM path: masked rows feed colmax only; skip dead stores
                    if (!CM || rr < qlim)
                        *(float2*)&Cf[rr * (long)ldc + c] = make_float2(v0, v1);
                }
                if (OUT >= 1) {
                    __half h0 = __float2half_rn(v0), h1 = __float2half_rn(v1);
                    *(__half2*)&Chi[rr * (long)ldc + c] = __halves2half2(h0, h1);
                    if (OUT == 2) {
                        __half l0 = __float2half_rn(v0 - __half2float(h0));
                        __half l1 = __float2half_rn(v1 - __half2float(h1));
                        *(__half2*)&Clo[rr * (long)ldc + c] = __halves2half2(l0, l1);
                    }
                }
            }
        }
    }
    if (CM) {
        #pragma unroll
        for (int j = 0; j < NT; j++) {
            #pragma unroll
            for (int s = 4; s <= 16; s <<= 1) {
                colm[j][0] = fmaxf(colm[j][0], __shfl_xor_sync(0xffffffffu, colm[j][0], s));
                colm[j][1] = fmaxf(colm[j][1], __shfl_xor_sync(0xffffffffu, colm[j][1], s));
            }
        }
        if (frow == 0) {
            #pragma unroll
            for (int j = 0; j < NT; j++) {
                int c = col0 + warp_n * 32 + j * 8 + 2 * fcol;
                atomicMaxFloat(&cmaxp[c],     colm[j][0]);
                atomicMaxFloat(&cmaxp[c + 1], colm[j][1]);
            }
        }
    }
}

constexpr int smem4(bool TBB, bool SPLIT, int NS) {
    int APL = 128 * 40, NSP = SPLIT ? 2 : 1;
    int BPL = TBB ? APL : 32 * 136;
    return 2 * NS * NSP * (APL + BPL);
}

// ============ fused two-pass softmax + AV (fp16 MMA), qmask skipping ========
// grid (T/128, HB), 256 threads. p tile [128][72] halves; V tile [64][72].
// Row-level skip: rows q >= qmasks[b] are zeroed by the qmask after softmax.
// Tile-level skip: blocks with q0 >= qmasks[b] output pure residual.
constexpr int FS_PB   = 0;
constexpr int FS_VB   = FS_PB + 2 * 128 * 72 * 2;      // 36864
constexpr int FS_CM   = FS_VB + 2 * 64 * 72 * 2;       // 55296
constexpr int FS_MM   = FS_CM + 512 * 4;               // 57344
constexpr int FS_SS   = FS_MM + 128 * 4;               // 57856
constexpr int FS_SMEM = FS_SS + 128 * 4;               // 58368

__global__ __launch_bounds__(256, 2) void fsav_kernel(
    const float* __restrict__ S,
    const float* __restrict__ cmax,
    const __half* __restrict__ Vh,
    const float* __restrict__ q1f,
    const int* __restrict__ qmasks,
    float* __restrict__ Rf, __half* __restrict__ Rh)
{
    extern __shared__ char fs[];
    float* cm  = (float*)(fs + FS_CM);
    float* smM = (float*)(fs + FS_MM);
    float* smS = (float*)(fs + FS_SS);
    const uint32_t sbase = smem_u32(fs);

    const int tid = threadIdx.x, lane = tid & 31, wid = tid >> 5;
    const int q0 = blockIdx.x * 128;
    const int z  = blockIdx.y;
    const int hh = z / B_, b = z % B_;
    const float*  Sz = S + (long)z * T_ * T_;
    const __half* Vz = Vh + (long)b * T_ * D_ + hh * DH_;
    const float*  Qz = q1f + (long)b * T_ * D_ + hh * DH_;
    float*  Rfz = Rf + (long)b * T_ * D_ + hh * DH_;
    __half* Rhz = Rh + (long)b * T_ * D_ + hh * DH_;
    const int qlim = qmasks[b];

    // ---- tile-level early exit: whole q-tile masked -> R = q1 residual ----
    if (q0 >= qlim) {
        #pragma unroll
        for (int i = 0; i < 16; i++) {
            int idx = i * 256 + tid;
            int r = idx >> 5;
            int c2 = (idx & 31) * 2;
            long off = (long)(q0 + r) * D_ + c2;
            float2 v = *(const float2*)&Qz[off];
            *(float2*)&Rfz[off] = v;
            *(__half2*)&Rhz[off] = __floats2half2_rn(v.x, v.y);
        }
        return;
    }

    cm[tid]       = cmax[z * T_ + tid];
    cm[tid + 256] = cmax[z * T_ + tid + 256];
    __syncthreads();

    // ---- phase 1: per-row max & sum (one warp per row); skip masked rows ----
    for (int it = 0; it < 16; it++) {
        int r = it * 8 + wid;
        if (q0 + r >= qlim) {
            if (lane == 0) { smM[r] = 0.f; smS[r] = 1.f; }
            continue;
        }
        const float* Srow = Sz + (long)(q0 + r) * T_;
        float x[16];
        #pragma unroll
        for (int seg = 0; seg < 4; seg++) {
            float4 v = *(const float4*)(Srow + seg * 128 + lane * 4);
            int c = seg * 128 + lane * 4;
            x[seg * 4 + 0] = v.x - cm[c + 0];
            x[seg * 4 + 1] = v.y - cm[c + 1];
            x[seg * 4 + 2] = v.z - cm[c + 2];
            x[seg * 4 + 3] = v.w - cm[c + 3];
        }
        float m = x[0];
        #pragma unroll
        for (int j = 1; j < 16; j++) m = fmaxf(m, x[j]);
        #pragma unroll
        for (int o = 16; o; o >>= 1) m = fmaxf(m, __shfl_xor_sync(0xffffffffu, m, o));
        float s = 0.f;
        #pragma unroll
        for (int j = 0; j < 16; j++) s += expf(x[j] - m);
        #pragma unroll
        for (int o = 16; o; o >>= 1) s += __shfl_xor_sync(0xffffffffu, s, o);
        if (lane == 0) { smM[r] = m; smS[r] = s; }
    }
    __syncthreads();

    // ---- phase 2: stream k-tiles of 64: regenerate p (fp16), MMA with V ----
    const int warp_m = wid & 3, warp_n = wid >> 2;  // WM=32 (MT=2), WN=32 (NT=4)
    const int frow = lane >> 2, fcol = lane & 3;

    float acc[2][4][4];
    #pragma unroll
    for (int i = 0; i < 2; i++)
        #pragma unroll
        for (int j = 0; j < 4; j++)
            #pragma unroll
            for (int q = 0; q < 4; q++) acc[i][j][q] = 0.f;

    auto loadV = [&](int buf, int k0) {
        #pragma unroll
        for (int i = 0; i < 2; i++) {
            int idx = i * 256 + tid;
            int row = idx >> 3, c8 = (idx & 7) * 8;
            cpa16(sbase + (uint32_t)(FS_VB + (buf * 64 * 72 + row * 72 + c8) * 2),
                  Vz + (long)(k0 + row) * D_ + c8);
        }
    };
    auto genP = [&](int buf, int k0) {
        __half* pt = (__half*)(fs + FS_PB) + buf * 128 * 72;
        #pragma unroll
        for (int pass = 0; pass < 8; pass++) {
            int r = pass * 16 + (tid >> 4);
            int c4 = (tid & 15) * 4;
            if (q0 + r >= qlim) {
                *(__half2*)&pt[r * 72 + c4]     = __halves2half2(__ushort_as_half(0),
                                                                 __ushort_as_half(0));
                *(__half2*)&pt[r * 72 + c4 + 2] = __halves2half2(__ushort_as_half(0),
                                                                 __ushort_as_half(0));
                continue;
            }
            float4 v = *(const float4*)(Sz + (long)(q0 + r) * T_ + k0 + c4);
            float mm = smM[r];
            __half2 p0 = __floats2half2_rn(expf(v.x - cm[k0 + c4 + 0] - mm),
                                           expf(v.y - cm[k0 + c4 + 1] - mm));
            __half2 p1 = __floats2half2_rn(expf(v.z - cm[k0 + c4 + 2] - mm),
                                           expf(v.w - cm[k0 + c4 + 3] - mm));
            *(__half2*)&pt[r * 72 + c4]     = p0;
            *(__half2*)&pt[r * 72 + c4 + 2] = p1;
        }
    };

    loadV(0, 0); CPA_COMMIT();

    for (int kt = 0; kt < 8; kt++) {
        int buf = kt & 1;
        genP(buf, kt * 64);
        CPA_WAIT0();
        __syncthreads();
        if (kt + 1 < 8) { loadV(buf ^ 1, (kt + 1) * 64); CPA_COMMIT(); }
        const uint32_t pB = sbase + (uint32_t)(FS_PB + buf * 128 * 72 * 2);
        const uint32_t vB = sbase + (uint32_t)(FS_VB + buf * 64 * 72 * 2);
        #pragma unroll
        for (int ks = 0; ks < 4; ks++) {
            const int kk = ks * 16;
            uint32_t af[2][4], bf[4][2];
            #pragma unroll
            for (int i = 0; i < 2; i++)
                ldsm_x4(af[i], pB + (uint32_t)((warp_m * 32 + i * 16 + (lane & 15)) * 72
                                               + kk + (lane >> 4) * 8) * 2);
            #pragma unroll
            for (int j = 0; j < 4; j++)
                ldsm_x2t(bf[j], vB + (uint32_t)((kk + (lane & 15)) * 72
                                                + warp_n * 32 + j * 8) * 2);
            #pragma unroll
            for (int i = 0; i < 2; i++)
                #pragma unroll
                for (int j = 0; j < 4; j++)
                    mma16n8k16(acc[i][j], af[i], bf[j]);
        }
        __syncthreads();
    }

    // ---- epilogue: scale by qmask/sum, add residual, write fp32 + fp16 ----
    #pragma unroll
    for (int i = 0; i < 2; i++) {
        #pragma unroll
        for (int j = 0; j < 4; j++) {
            int rloc = warp_m * 32 + i * 16 + frow;
            int c = warp_n * 32 + j * 8 + 2 * fcol;
            #pragma unroll
            for (int h = 0; h < 2; h++) {
                int rr = rloc + h * 8;
                float inv = ((q0 + rr) < qlim ? 1.f : 0.f) / smS[rr];
                long off = (long)(q0 + rr) * D_ + c;
                float v0 = acc[i][j][2 * h] * inv + Qz[off];
                float v1 = acc[i][j][2 * h + 1] * inv + Qz[off + 1];
                *(float2*)&Rfz[off] = make_float2(v0, v1);
                *(__half2*)&Rhz[off] = __floats2half2_rn(v0, v1);
            }
        }
    }
}

// ---------------- positional encoding (fp64 to match numpy) -----------------
__global__ void pe_kernel(float* __restrict__ pe) {
    int idx = blockIdx.x * blockDim.x + threadIdx.x;
    if (idx >= T_ * D_) return;
    int t = idx / D_;
    int d = idx % D_;
    double ang = (double)t * exp(-(2.0 * (double)d / (double)D_) * log(10000.0));
    double v = (d & 1) ? cos(ang) : sin(ang);
    pe[idx] = (float)(v * sqrt((double)D_));
}

__global__ void addpe2_kernel(const float* __restrict__ q, const float* __restrict__ pe,
                              float* __restrict__ q1f,
                              __half* __restrict__ q1h, __half* __restrict__ q1l,
                              __half* __restrict__ k1h, __half* __restrict__ k1l) {
    long idx = (long)blockIdx.x * blockDim.x + threadIdx.x;
    long td = idx % ((long)T_ * D_);
    float p = pe[td];
    float a = q[idx] + p;
    q1f[idx] = a;
    __half ah = __float2half_rn(a);
    q1h[idx] = ah;
    q1l[idx] = __float2half_rn(a - __half2float(ah));
    float bb = a + p;                      // k1 = q1 + pe (source bug kept)
    __half bh = __float2half_rn(bb);
    k1h[idx] = bh;
    k1l[idx] = __float2half_rn(bb - __half2float(bh));
}

// single fused conversion kernel: all weights + cmax init
__global__ void cvt_all_kernel(const float* __restrict__ wq, const float* __restrict__ wk,
                               const float* __restrict__ wv, const float* __restrict__ f1,
                               const float* __restrict__ f2,
                               __half* __restrict__ wqh, __half* __restrict__ wql,
                               __half* __restrict__ wkh, __half* __restrict__ wkl,
                               __half* __restrict__ wvh,
                               __half* __restrict__ f1h, __half* __restrict__ f2h,
                               float* __restrict__ cmaxp) {
    constexpr int DD = D_ * D_;
    constexpr int DF = D_ * FF_;
    int i = blockIdx.x * blockDim.x + threadIdx.x;
    if (i < DD) {
        float x = wq[i];
        __half h = __float2half_rn(x);
        wqh[i] = h;
        wql[i] = __float2half_rn(x - __half2float(h));
    } else if (i < 2 * DD) {
        int j = i - DD;
        float x = wk[j];
        __half h = __float2half_rn(x);
        wkh[j] = h;
        wkl[j] = __float2half_rn(x - __half2float(h));
    } else if (i < 3 * DD) {
        int j = i - 2 * DD;
        wvh[j] = __float2half_rn(wv[j]);
    } else if (i < 3 * DD + DF) {
        int j = i - 3 * DD;
        f1h[j] = __float2half_rn(f1[j]);
    } else if (i < 3 * DD + 2 * DF) {
        int j = i - 3 * DD - DF;
        f2h[j] = __float2half_rn(f2[j]);
    } else if (i < 3 * DD + 2 * DF + HB_ * T_) {
        cmaxp[i - 3 * DD - 2 * DF] = -INFINITY;
    }
}

// ---------------- launch -----------------------------------------------------
extern "C" void kernel_launch(void* const* d_in, const int* in_sizes, int n_in,
                              void* d_out, int out_size) {
    const float* queries = (const float*)d_in[0];
    const int*   qmasks  = (const int*)d_in[2];
    const float* W_Q = (const float*)d_in[4];
    const float* W_K = (const float*)d_in[5];
    const float* W_V = (const float*)d_in[6];
    const float* fw1 = (const float*)d_in[7];
    const float* fw2 = (const float*)d_in[8];
    float* out = (float*)d_out;

    float *pe, *q1f, *S, *cmax, *R;
    __half *q1h, *q1l, *k1h, *k1l, *Qh, *Ql, *Kh, *Kl, *Vh, *Rh, *Hd;
    __half *wqh, *wql, *wkh, *wkl, *wvh, *f1h, *f2h;
    cudaGetSymbolAddress((void**)&pe,  g_pe);
    cudaGetSymbolAddress((void**)&q1f, g_q1);
    cudaGetSymbolAddress((void**)&q1h, g_q1h);
    cudaGetSymbolAddress((void**)&q1l, g_q1l);
    cudaGetSymbolAddress((void**)&k1h, g_k1h);
    cudaGetSymbolAddress((void**)&k1l, g_k1l);
    cudaGetSymbolAddress((void**)&Qh,  g_Qh);
    cudaGetSymbolAddress((void**)&Ql,  g_Ql);
    cudaGetSymbolAddress((void**)&Kh,  g_Kh);
    cudaGetSymbolAddress((void**)&Kl,  g_Kl);
    cudaGetSymbolAddress((void**)&Vh,  g_Vh);
    cudaGetSymbolAddress((void**)&S,   g_S);
    cudaGetSymbolAddress((void**)&cmax, g_cmax);
    cudaGetSymbolAddress((void**)&R,   g_R);
    cudaGetSymbolAddress((void**)&Rh,  g_Rh);
    cudaGetSymbolAddress((void**)&Hd,  g_H);
    cudaGetSymbolAddress((void**)&wqh, g_wqh);
    cudaGetSymbolAddress((void**)&wql, g_wql);
    cudaGetSymbolAddress((void**)&wkh, g_wkh);
    cudaGetSymbolAddress((void**)&wkl, g_wkl);
    cudaGetSymbolAddress((void**)&wvh, g_wvh);
    cudaGetSymbolAddress((void**)&f1h, g_f1h);
    cudaGetSymbolAddress((void**)&f2h, g_f2h);

    const long TD = (long)T_ * D_;
    const long TT = (long)T_ * T_;

    constexpr int SM_PLAIN = smem4(false, false, 3);  // 56832
    constexpr int SM_SPL3  = smem4(false, true,  3);  // 113664 (2 CTAs: 227328)
    constexpr int SM_SPL1  = smem4(true,  true,  2);  // 81920

    cudaFuncSetAttribute((const void*)mma4<false, true,  2, false, 3, true>,
                         cudaFuncAttributeMaxDynamicSharedMemorySize, SM_SPL3);
    cudaFuncSetAttribute((const void*)mma4<true,  true,  0, true,  2, false>,
                         cudaFuncAttributeMaxDynamicSharedMemorySize, SM_SPL1);
    cudaFuncSetAttribute((const void*)mma4<false, false, 1, false, 3, false>,
                         cudaFuncAttributeMaxDynamicSharedMemorySize, SM_PLAIN);
    cudaFuncSetAttribute((const void*)mma4<false, false, 0, false, 3, false>,
                         cudaFuncAttributeMaxDynamicSharedMemorySize, SM_PLAIN);
    cudaFuncSetAttribute((const void*)fsav_kernel,
                         cudaFuncAttributeMaxDynamicSharedMemorySize, FS_SMEM);

    // 1) posenc + all conversions (+cmax init)
    pe_kernel<<<(T_ * D_ + 255) / 256, 256>>>(pe);
    addpe2_kernel<<<(B_ * T_ * D_) / 256, 256>>>(queries, pe, q1f, q1h, q1l, k1h, k1l);
    {
        int n = 3 * D_ * D_ + 2 * D_ * FF_ + HB_ * T_;
        cvt_all_kernel<<<(n + 255) / 256, 256>>>(W_Q, W_K, W_V, fw1, fw2,
                                                 wqh, wql, wkh, wkl, wvh, f1h, f2h, cmax);
    }

    // 2) Q and K projections batched in one DUAL launch (fp16 split, 3-stage)
    {
        dim3 g(D_ / 128, (B_ * T_) / 128, 2);
        mma4<false, true, 2, false, 3, true><<<g, 256, SM_SPL3>>>(
            q1h, q1l, 0, 0, D_, wqh, wql, 0, 0, D_,
            nullptr, Qh, Ql, 0, 0, D_, nullptr, 0, 0, 0, nullptr, nullptr, 1, D_, 1.f, 0,
            k1h, k1l, wkh, wkl, Kh, Kl);
    }

    // 3) V projection: V = Kp @ W_V (bug kept) -> fp16 (3-stage)
    {
        dim3 g(D_ / 128, (B_ * T_) / 128, 1);
        mma4<false, false, 1, false, 3, false><<<g, 256, SM_PLAIN>>>(
            Kh, nullptr, 0, 0, D_, wvh, nullptr, 0, 0, D_,
            nullptr, Vh, nullptr, 0, 0, D_, nullptr, 0, 0, 0, nullptr, nullptr, 1, D_, 1.f, 0,
            nullptr, nullptr, nullptr, nullptr, nullptr, nullptr);
    }

    // 4) scores (fp16 split, B=[N][K]) -> fp32 S + fused column-max atomics
    //    masked rows (q >= qmasks[b]) feed colmax only; their S stores skipped
    {
        dim3 g(T_ / 128, T_ / 128, HB_);
        mma4<true, true, 0, true, 2, false><<<g, 256, SM_SPL1>>>(
            Qh, Ql, DH_, TD, D_,
            Kh, Kl, DH_, TD, D_,
            S, nullptr, nullptr, (long)B_ * TT, TT, T_,
            nullptr, 0, 0, 0, cmax, qmasks,
            B_, DH_, 0.125f, 0,
            nullptr, nullptr, nullptr, nullptr, nullptr, nullptr);
    }

    // 5) fused two-pass softmax + AV with qmask row- and tile-skip
    {
        dim3 g(T_ / 128, HB_);
        fsav_kernel<<<g, 256, FS_SMEM>>>(S, cmax, Vh, q1f, qmasks, R, Rh);
    }

    // 6) FFN1: hidden = relu(R @ fw1) -> fp16 (3-stage)
    {
        dim3 g(FF_ / 128, (B_ * T_) / 128, 1);
        mma4<false, false, 1, false, 3, false><<<g, 256, SM_PLAIN>>>(
            Rh, nullptr, 0, 0, D_, f1h, nullptr, 0, 0, FF_,
            nullptr, Hd, nullptr, 0, 0, FF_, nullptr, 0, 0, 0, nullptr, nullptr, 1, D_, 1.f, 1,
            nullptr, nullptr, nullptr, nullptr, nullptr, nullptr);
    }

    // 7) FFN2: out = R + hidden @ fw2 -> fp32 (3-stage)
    {
        dim3 g(D_ / 128, (B_ * T_) / 128, 1);
        mma4<false, false, 0, false, 3, false><<<g, 256, SM_PLAIN>>>(
            Hd, nullptr, 0, 0, FF_, f2h, nullptr, 0, 0, D_,
            out, nullptr, nullptr, 0, 0, D_, R, 0, 0, D_, nullptr, nullptr, 1, FF_, 1.f, 0,
            nullptr, nullptr, nullptr, nullptr, nullptr, nullptr);
    }
}

// round 15
// speedup vs baseline: 1.1061x; 1.0310x over previous
#include <cuda_runtime.h>
#include <cuda_fp16.h>
#include <math.h>
#include <stdint.h>

// Problem constants
constexpr int B_  = 32;
constexpr int T_  = 512;
constexpr int D_  = 512;
constexpr int H_  = 8;
constexpr int DH_ = 64;
constexpr int HB_ = H_ * B_;        // 256
constexpr int FF_ = 4 * D_;         // 2048

// ---------------- scratch (static device globals; allocation-free) ----------
__device__ float  g_pe [T_ * D_];
__device__ float  g_q1 [B_ * T_ * D_];              // fp32 residual
__device__ __half g_q1h[B_ * T_ * D_];
__device__ __half g_q1l[B_ * T_ * D_];
__device__ __half g_k1h[B_ * T_ * D_];
__device__ __half g_k1l[B_ * T_ * D_];
__device__ __half g_Qh [B_ * T_ * D_];
__device__ __half g_Ql [B_ * T_ * D_];
__device__ __half g_Kh [B_ * T_ * D_];
__device__ __half g_Kl [B_ * T_ * D_];
__device__ __half g_Vh [B_ * T_ * D_];
__device__ float  g_S  [(long)HB_ * T_ * T_];       // 256MB fp32 scores
__device__ __half g_P  [(long)HB_ * T_ * T_];       // 128MB fp16 exp cache
__device__ float  g_cmax[HB_ * T_];
__device__ float  g_R  [B_ * T_ * D_];              // fp32 residual
__device__ __half g_Rh [B_ * T_ * D_];
__device__ __half g_H  [(long)B_ * T_ * FF_];       // hidden (fp16), 64MB
// converted weights
__device__ __half g_wqh[D_ * D_], g_wql[D_ * D_];
__device__ __half g_wkh[D_ * D_], g_wkl[D_ * D_];
__device__ __half g_wvh[D_ * D_];
__device__ __half g_f1h[D_ * FF_];
__device__ __half g_f2h[FF_ * D_];

// ---------------- helpers ---------------------------------------------------
__device__ __forceinline__ void mma16n8k16(float* c, const uint32_t* a, const uint32_t* b) {
    asm volatile(
        "mma.sync.aligned.m16n8k16.row.col.f32.f16.f16.f32 "
        "{%0,%1,%2,%3}, {%4,%5,%6,%7}, {%8,%9}, {%0,%1,%2,%3};"
        : "+f"(c[0]), "+f"(c[1]), "+f"(c[2]), "+f"(c[3])
        : "r"(a[0]), "r"(a[1]), "r"(a[2]), "r"(a[3]), "r"(b[0]), "r"(b[1]));
}
__device__ __forceinline__ void ldsm_x4(uint32_t* r, uint32_t a) {
    asm volatile("ldmatrix.sync.aligned.m8n8.x4.shared.b16 {%0,%1,%2,%3}, [%4];"
        : "=r"(r[0]), "=r"(r[1]), "=r"(r[2]), "=r"(r[3]) : "r"(a));
}
__device__ __forceinline__ void ldsm_x2(uint32_t* r, uint32_t a) {
    asm volatile("ldmatrix.sync.aligned.m8n8.x2.shared.b16 {%0,%1}, [%2];"
        : "=r"(r[0]), "=r"(r[1]) : "r"(a));
}
__device__ __forceinline__ void ldsm_x2t(uint32_t* r, uint32_t a) {
    asm volatile("ldmatrix.sync.aligned.m8n8.x2.trans.shared.b16 {%0,%1}, [%2];"
        : "=r"(r[0]), "=r"(r[1]) : "r"(a));
}
__device__ __forceinline__ uint32_t smem_u32(const void* p) {
    uint32_t a;
    asm("{ .reg .u64 t; cvta.to.shared.u64 t, %1; cvt.u32.u64 %0, t; }"
        : "=r"(a) : "l"(p));
    return a;
}
// cp.async with L1 bypass (.cg): keeps L1 bandwidth free for ldmatrix
__device__ __forceinline__ void cpa16(uint32_t saddr, const void* g) {
    asm volatile("cp.async.cg.shared.global [%0], [%1], 16;"
                 :: "r"(saddr), "l"(g) : "memory");
}
#define CPA_COMMIT() asm volatile("cp.async.commit_group;" ::: "memory")
#define CPA_WAIT1()  asm volatile("cp.async.wait_group 1;" ::: "memory")
#define CPA_WAIT0()  asm volatile("cp.async.wait_group 0;" ::: "memory")

__device__ __forceinline__ void atomicMaxFloat(float* addr, float v) {
    if (v >= 0.f) atomicMax((int*)addr, __float_as_int(v));
    else          atomicMin((unsigned int*)addr, __float_as_uint(v));
}

// ============ fp16 mma.sync GEMM engine v4 (ldmatrix + cp.async) ============
// Block tile 128x128, BK=32, 256 threads (8 warps: nWM=2, nWN=4; WM=64, WN=32).
// A row-major [M][K] fp16. B: TBB=0 -> [K][N]; TBB=1 -> [N][K].
// SPLIT: hi/lo planes, 3 MMAs. OUT: 0=fp32; 1=fp16 hi; 2=fp16 hi+lo.
// CM: fused column-max atomics; with qm_p set, rows rr >= qm_p[i2] are not
//     stored to C (they only feed the colmax; consumer never reads them).
// DUAL: blockIdx.z==1 selects alternate tensors.
// NS: pipeline depth (2 = preload-all fast path, requires K/BK <= 2; 3 = ring).
template<bool TBB, bool SPLIT, int OUT, bool CM, int NS, bool DUAL>
__global__ void __launch_bounds__(256, 2) mma4(
    const __half* __restrict__ Ah_g, const __half* __restrict__ Al_g,
    long sA1, long sA2, int lda,
    const __half* __restrict__ Bh_g, const __half* __restrict__ Bl_g,
    long sB1, long sB2, int ldb,
    float* Cf, __half* Chi, __half* Clo, long sC1, long sC2, int ldc,
    const float* __restrict__ Res, long sR1, long sR2, int ldres,
    float* cmaxp, const int* __restrict__ qm_p,
    int nb2, int K, float alpha, int relu,
    const __half* A2h, const __half* A2l,
    const __half* B2h, const __half* B2l,
    __half* C2hi, __half* C2lo)
{
    constexpr int BK  = 32;
    constexpr int AP  = 40;                 // A pitch (halves)
    constexpr int APL = 128 * AP;
    constexpr int NSP = SPLIT ? 2 : 1;
    constexpr int ASZ = NSP * APL;
    constexpr int BP  = 136;                // [K][N] B pitch
    constexpr int BPL = TBB ? APL : BK * BP;
    constexpr int BSZ = NSP * BPL;
    constexpr int STG = ASZ + BSZ;
    constexpr int MT  = 4;
    constexpr int NT  = 4;

    extern __shared__ __half smh[];
    const uint32_t sbase = smem_u32(smh);

    int z  = blockIdx.z;
    int qlim = 1 << 30;                      // default: store all rows
    if (DUAL && z == 1) {
        Ah_g = A2h; Al_g = A2l; Bh_g = B2h; Bl_g = B2l;
        Chi = C2hi; Clo = C2lo;
    } else {
        int i1 = z / nb2, i2 = z % nb2;
        Ah_g += i1 * sA1 + i2 * sA2;
        if (SPLIT) Al_g += i1 * sA1 + i2 * sA2;
        Bh_g += i1 * sB1 + i2 * sB2;
        if (SPLIT) Bl_g += i1 * sB1 + i2 * sB2;
        if (OUT == 0) Cf  += i1 * sC1 + i2 * sC2;
        if (OUT >= 1) Chi += i1 * sC1 + i2 * sC2;
        if (OUT == 2) Clo += i1 * sC1 + i2 * sC2;
        if (Res) Res += i1 * sR1 + i2 * sR2;
        if (CM) {
            cmaxp += (long)z * ldc;
            if (qm_p) qlim = qm_p[i2];       // scores: i2 = batch index
        }
    }

    const int tid  = threadIdx.x;
    const int lane = tid & 31;
    const int wid  = tid >> 5;
    const int warp_m = wid & 1;
    const int warp_n = wid >> 1;
    const int row0 = blockIdx.y * 128;
    const int col0 = blockIdx.x * 128;
    const int frow = lane >> 2, fcol = lane & 3;

    float acc[MT][NT][4];
    #pragma unroll
    for (int i = 0; i < MT; i++)
        #pragma unroll
        for (int j = 0; j < NT; j++)
            #pragma unroll
            for (int q = 0; q < 4; q++) acc[i][j][q] = 0.f;

    auto load_stage = [&](int st, int k0) {
        uint32_t sA = sbase + (uint32_t)(st * STG) * 2;
        #pragma unroll
        for (int i = 0; i < 2 * NSP; i++) {
            int idx = i * 256 + tid;
            int plane = idx >> 9;
            int rem = idx & 511;
            int row = rem >> 2, c8 = (rem & 3) * 8;
            const __half* g = (SPLIT && plane ? Al_g : Ah_g)
                            + (long)(row0 + row) * lda + k0 + c8;
            cpa16(sA + (uint32_t)(plane * APL + row * AP + c8) * 2, g);
        }
        uint32_t sB = sbase + (uint32_t)(st * STG + ASZ) * 2;
        if (TBB) {
            #pragma unroll
            for (int i = 0; i < 2 * NSP; i++) {
                int idx = i * 256 + tid;
                int plane = idx >> 9;
                int rem = idx & 511;
                int row = rem >> 2, c8 = (rem & 3) * 8;
                const __half* g = (SPLIT && plane ? Bl_g : Bh_g)
                                + (long)(col0 + row) * ldb + k0 + c8;
                cpa16(sB + (uint32_t)(plane * APL + row * AP + c8) * 2, g);
            }
        } else {
            #pragma unroll
            for (int i = 0; i < 2 * NSP; i++) {
                int idx = i * 256 + tid;
                int plane = idx >> 9;
                int rem = idx & 511;
                int row = rem >> 4, c8 = (rem & 15) * 8;
                const __half* g = (SPLIT && plane ? Bl_g : Bh_g)
                                + (long)(k0 + row) * ldb + col0 + c8;
                cpa16(sB + (uint32_t)(plane * BPL + row * BP + c8) * 2, g);
            }
        }
    };

    auto compute = [&](int st) {
        const uint32_t aB = sbase + (uint32_t)(st * STG) * 2;
        const uint32_t bB = aB + (uint32_t)ASZ * 2;
        #pragma unroll
        for (int ks = 0; ks < 2; ks++) {
            const int kk = ks * 16;
            uint32_t af[MT][4], bh[NT][2];
            #pragma unroll
            for (int i = 0; i < MT; i++)
                ldsm_x4(af[i], aB + (uint32_t)((warp_m * 64 + i * 16 + (lane & 15)) * AP
                                               + kk + (lane >> 4) * 8) * 2);
            #pragma unroll
            for (int j = 0; j < NT; j++) {
                if (TBB)
                    ldsm_x2(bh[j], bB + (uint32_t)((warp_n * 32 + j * 8 + (lane & 7)) * AP
                                                   + kk + ((lane >> 3) & 1) * 8) * 2);
                else
                    ldsm_x2t(bh[j], bB + (uint32_t)((kk + (lane & 15)) * BP
                                                    + warp_n * 32 + j * 8) * 2);
            }
            #pragma unroll
            for (int i = 0; i < MT; i++)
                #pragma unroll
                for (int j = 0; j < NT; j++)
                    mma16n8k16(acc[i][j], af[i], bh[j]);
            if (SPLIT) {
                uint32_t b2[NT][2];
                #pragma unroll
                for (int j = 0; j < NT; j++) {
                    if (TBB)
                        ldsm_x2(b2[j], bB + (uint32_t)(APL + (warp_n * 32 + j * 8 + (lane & 7)) * AP
                                                       + kk + ((lane >> 3) & 1) * 8) * 2);
                    else
                        ldsm_x2t(b2[j], bB + (uint32_t)(BPL + (kk + (lane & 15)) * BP
                                                        + warp_n * 32 + j * 8) * 2);
                }
                #pragma unroll
                for (int i = 0; i < MT; i++)
                    #pragma unroll
                    for (int j = 0; j < NT; j++)
                        mma16n8k16(acc[i][j], af[i], b2[j]);
                #pragma unroll
                for (int i = 0; i < MT; i++)
                    ldsm_x4(af[i], aB + (uint32_t)(APL + (warp_m * 64 + i * 16 + (lane & 15)) * AP
                                                   + kk + (lane >> 4) * 8) * 2);
                #pragma unroll
                for (int i = 0; i < MT; i++)
                    #pragma unroll
                    for (int j = 0; j < NT; j++)
                        mma16n8k16(acc[i][j], af[i], bh[j]);
            }
        }
    };

    const int NTL = K / BK;
    if (NS == 3) {
        load_stage(0, 0);   CPA_COMMIT();
        load_stage(1, BK);  CPA_COMMIT();
        for (int kt = 0; kt < NTL; kt++) {
            CPA_WAIT1();
            __syncthreads();
            if (kt + 2 < NTL) load_stage((kt + 2) % 3, (kt + 2) * BK);
            CPA_COMMIT();
            compute(kt % 3);
        }
    } else {
        // NS == 2 fast path: K/BK <= 2 guaranteed by call sites.
        load_stage(0, 0);
        if (NTL > 1) load_stage(1, BK);
        CPA_COMMIT();
        CPA_WAIT0();
        __syncthreads();
        compute(0);
        if (NTL > 1) compute(1);
    }

    // ---- epilogue ----
    float colm[NT][2];
    if (CM) {
        #pragma unroll
        for (int j = 0; j < NT; j++) { colm[j][0] = -INFINITY; colm[j][1] = -INFINITY; }
    }
    #pragma unroll
    for (int i = 0; i < MT; i++) {
        #pragma unroll
        for (int j = 0; j < NT; j++) {
            int r = row0 + warp_m * 64 + i * 16 + frow;
            int c = col0 + warp_n * 32 + j * 8 + 2 * fcol;
            #pragma unroll
            for (int h = 0; h < 2; h++) {
                long rr = r + h * 8;
                float v0 = acc[i][j][2 * h] * alpha;
                float v1 = acc[i][j][2 * h + 1] * alpha;
                if (Res) {
                    v0 += Res[rr * (long)ldres + c];
                    v1 += Res[rr * (long)ldres + c + 1];
                }
                if (relu) { v0 = fmaxf(v0, 0.f); v1 = fmaxf(v1, 0.f); }
                if (CM) {
                    colm[j][0] = fmaxf(colm[j][0], v0);
                    colm[j][1] = fmaxf(colm[j][1], v1);
                }
                if (OUT == 0) {
                    if (!CM || rr < qlim)
                        *(float2*)&Cf[rr * (long)ldc + c] = make_float2(v0, v1);
                }
                if (OUT >= 1) {
                    __half h0 = __float2half_rn(v0), h1 = __float2half_rn(v1);
                    *(__half2*)&Chi[rr * (long)ldc + c] = __halves2half2(h0, h1);
                    if (OUT == 2) {
                        __half l0 = __float2half_rn(v0 - __half2float(h0));
                        __half l1 = __float2half_rn(v1 - __half2float(h1));
                        *(__half2*)&Clo[rr * (long)ldc + c] = __halves2half2(l0, l1);
                    }
                }
            }
        }
    }
    if (CM) {
        #pragma unroll
        for (int j = 0; j < NT; j++) {
            #pragma unroll
            for (int s = 4; s <= 16; s <<= 1) {
                colm[j][0] = fmaxf(colm[j][0], __shfl_xor_sync(0xffffffffu, colm[j][0], s));
                colm[j][1] = fmaxf(colm[j][1], __shfl_xor_sync(0xffffffffu, colm[j][1], s));
            }
        }
        if (frow == 0) {
            #pragma unroll
            for (int j = 0; j < NT; j++) {
                int c = col0 + warp_n * 32 + j * 8 + 2 * fcol;
                atomicMaxFloat(&cmaxp[c],     colm[j][0]);
                atomicMaxFloat(&cmaxp[c + 1], colm[j][1]);
            }
        }
    }
}

constexpr int smem4(bool TBB, bool SPLIT, int NS) {
    int APL = 128 * 40, NSP = SPLIT ? 2 : 1;
    int BPL = TBB ? APL : 32 * 136;
    return 2 * NS * NSP * (APL + BPL);
}

// ============ fused two-pass softmax + AV (fp16 MMA), qmask skipping ========
// grid (T/128, HB), 256 threads. p tile [128][72] halves; V tile [64][72].
// Phase 1 computes exp once and caches fp16 p into g_P; phase 2 just copies.
// Row-level skip: rows q >= qmasks[b] zeroed. Tile-level skip: pure residual.
constexpr int FS_PB   = 0;
constexpr int FS_VB   = FS_PB + 2 * 128 * 72 * 2;      // 36864
constexpr int FS_CM   = FS_VB + 2 * 64 * 72 * 2;       // 55296
constexpr int FS_MM   = FS_CM + 512 * 4;               // 57344
constexpr int FS_SS   = FS_MM + 128 * 4;               // 57856
constexpr int FS_SMEM = FS_SS + 128 * 4;               // 58368

__global__ __launch_bounds__(256, 2) void fsav_kernel(
    const float* __restrict__ S,
    __half* __restrict__ P,
    const float* __restrict__ cmax,
    const __half* __restrict__ Vh,
    const float* __restrict__ q1f,
    const int* __restrict__ qmasks,
    float* __restrict__ Rf, __half* __restrict__ Rh)
{
    extern __shared__ char fs[];
    float* cm  = (float*)(fs + FS_CM);
    float* smM = (float*)(fs + FS_MM);
    float* smS = (float*)(fs + FS_SS);
    const uint32_t sbase = smem_u32(fs);

    const int tid = threadIdx.x, lane = tid & 31, wid = tid >> 5;
    const int q0 = blockIdx.x * 128;
    const int z  = blockIdx.y;
    const int hh = z / B_, b = z % B_;
    const float*  Sz = S + (long)z * T_ * T_;
    __half*       Pz = P + (long)z * T_ * T_;
    const __half* Vz = Vh + (long)b * T_ * D_ + hh * DH_;
    const float*  Qz = q1f + (long)b * T_ * D_ + hh * DH_;
    float*  Rfz = Rf + (long)b * T_ * D_ + hh * DH_;
    __half* Rhz = Rh + (long)b * T_ * D_ + hh * DH_;
    const int qlim = qmasks[b];

    // ---- tile-level early exit: whole q-tile masked -> R = q1 residual ----
    if (q0 >= qlim) {
        #pragma unroll
        for (int i = 0; i < 16; i++) {
            int idx = i * 256 + tid;
            int r = idx >> 5;
            int c2 = (idx & 31) * 2;
            long off = (long)(q0 + r) * D_ + c2;
            float2 v = *(const float2*)&Qz[off];
            *(float2*)&Rfz[off] = v;
            *(__half2*)&Rhz[off] = __floats2half2_rn(v.x, v.y);
        }
        return;
    }

    cm[tid]       = cmax[z * T_ + tid];
    cm[tid + 256] = cmax[z * T_ + tid + 256];
    __syncthreads();

    // ---- phase 1: per-row max & sum; cache p = exp(x-m) as fp16 in g_P ----
    for (int it = 0; it < 16; it++) {
        int r = it * 8 + wid;
        if (q0 + r >= qlim) {
            if (lane == 0) { smM[r] = 0.f; smS[r] = 1.f; }
            continue;
        }
        const float* Srow = Sz + (long)(q0 + r) * T_;
        float x[16];
        #pragma unroll
        for (int seg = 0; seg < 4; seg++) {
            float4 v = *(const float4*)(Srow + seg * 128 + lane * 4);
            int c = seg * 128 + lane * 4;
            x[seg * 4 + 0] = v.x - cm[c + 0];
            x[seg * 4 + 1] = v.y - cm[c + 1];
            x[seg * 4 + 2] = v.z - cm[c + 2];
            x[seg * 4 + 3] = v.w - cm[c + 3];
        }
        float m = x[0];
        #pragma unroll
        for (int j = 1; j < 16; j++) m = fmaxf(m, x[j]);
        #pragma unroll
        for (int o = 16; o; o >>= 1) m = fmaxf(m, __shfl_xor_sync(0xffffffffu, m, o));
        float e[16];
        float s = 0.f;
        #pragma unroll
        for (int j = 0; j < 16; j++) { e[j] = expf(x[j] - m); s += e[j]; }
        // cache p (fp16) — identical values genP used to recompute
        __half* Prow = Pz + (long)(q0 + r) * T_;
        #pragma unroll
        for (int seg = 0; seg < 4; seg++) {
            int c = seg * 128 + lane * 4;
            *(__half2*)&Prow[c]     = __floats2half2_rn(e[seg * 4 + 0], e[seg * 4 + 1]);
            *(__half2*)&Prow[c + 2] = __floats2half2_rn(e[seg * 4 + 2], e[seg * 4 + 3]);
        }
        #pragma unroll
        for (int o = 16; o; o >>= 1) s += __shfl_xor_sync(0xffffffffu, s, o);
        if (lane == 0) { smM[r] = m; smS[r] = s; }
    }
    __syncthreads();

    // ---- phase 2: stream k-tiles of 64: copy cached p, MMA with V ----
    const int warp_m = wid & 3, warp_n = wid >> 2;  // WM=32 (MT=2), WN=32 (NT=4)
    const int frow = lane >> 2, fcol = lane & 3;

    float acc[2][4][4];
    #pragma unroll
    for (int i = 0; i < 2; i++)
        #pragma unroll
        for (int j = 0; j < 4; j++)
            #pragma unroll
            for (int q = 0; q < 4; q++) acc[i][j][q] = 0.f;

    auto loadV = [&](int buf, int k0) {
        #pragma unroll
        for (int i = 0; i < 2; i++) {
            int idx = i * 256 + tid;
            int row = idx >> 3, c8 = (idx & 7) * 8;
            cpa16(sbase + (uint32_t)(FS_VB + (buf * 64 * 72 + row * 72 + c8) * 2),
                  Vz + (long)(k0 + row) * D_ + c8);
        }
    };
    auto genP = [&](int buf, int k0) {
        __half* pt = (__half*)(fs + FS_PB) + buf * 128 * 72;
        #pragma unroll
        for (int pass = 0; pass < 8; pass++) {
            int r = pass * 16 + (tid >> 4);
            int c4 = (tid & 15) * 4;
            if (q0 + r >= qlim) {
                *(uint2*)&pt[r * 72 + c4] = make_uint2(0u, 0u);
                continue;
            }
            uint2 pv = *(const uint2*)&Pz[(long)(q0 + r) * T_ + k0 + c4];
            *(uint2*)&pt[r * 72 + c4] = pv;
        }
    };

    loadV(0, 0); CPA_COMMIT();

    for (int kt = 0; kt < 8; kt++) {
        int buf = kt & 1;
        genP(buf, kt * 64);
        CPA_WAIT0();
        __syncthreads();
        if (kt + 1 < 8) { loadV(buf ^ 1, (kt + 1) * 64); CPA_COMMIT(); }
        const uint32_t pB = sbase + (uint32_t)(FS_PB + buf * 128 * 72 * 2);
        const uint32_t vB = sbase + (uint32_t)(FS_VB + buf * 64 * 72 * 2);
        #pragma unroll
        for (int ks = 0; ks < 4; ks++) {
            const int kk = ks * 16;
            uint32_t af[2][4], bf[4][2];
            #pragma unroll
            for (int i = 0; i < 2; i++)
                ldsm_x4(af[i], pB + (uint32_t)((warp_m * 32 + i * 16 + (lane & 15)) * 72
                                               + kk + (lane >> 4) * 8) * 2);
            #pragma unroll
            for (int j = 0; j < 4; j++)
                ldsm_x2t(bf[j], vB + (uint32_t)((kk + (lane & 15)) * 72
                                                + warp_n * 32 + j * 8) * 2);
            #pragma unroll
            for (int i = 0; i < 2; i++)
                #pragma unroll
                for (int j = 0; j < 4; j++)
                    mma16n8k16(acc[i][j], af[i], bf[j]);
        }
        __syncthreads();
    }

    // ---- epilogue: scale by qmask/sum, add residual, write fp32 + fp16 ----
    #pragma unroll
    for (int i = 0; i < 2; i++) {
        #pragma unroll
        for (int j = 0; j < 4; j++) {
            int rloc = warp_m * 32 + i * 16 + frow;
            int c = warp_n * 32 + j * 8 + 2 * fcol;
            #pragma unroll
            for (int h = 0; h < 2; h++) {
                int rr = rloc + h * 8;
                float inv = ((q0 + rr) < qlim ? 1.f : 0.f) / smS[rr];
                long off = (long)(q0 + rr) * D_ + c;
                float v0 = acc[i][j][2 * h] * inv + Qz[off];
                float v1 = acc[i][j][2 * h + 1] * inv + Qz[off + 1];
                *(float2*)&Rfz[off] = make_float2(v0, v1);
                *(__half2*)&Rhz[off] = __floats2half2_rn(v0, v1);
            }
        }
    }
}

// -------- positional encoding: double arg, float sincos on reduced arg ------
__global__ void pe_kernel(float* __restrict__ pe) {
    int idx = blockIdx.x * blockDim.x + threadIdx.x;
    if (idx >= T_ * D_) return;
    int t = idx / D_;
    int d = idx % D_;
    double ang = (double)t * exp(-(2.0 * (double)d / (double)D_) * log(10000.0));
    // exact-enough reduction to [0, 2pi) in double, then cheap float sin/cos
    const double TWO_PI = 6.283185307179586476925286766559;
    double rd = ang - TWO_PI * floor(ang / TWO_PI);
    float r = (float)rd;
    float v = (d & 1) ? cosf(r) : sinf(r);
    pe[idx] = v * 22.62741699796952078697f;   // sqrt(512)
}

__global__ void addpe2_kernel(const float* __restrict__ q, const float* __restrict__ pe,
                              float* __restrict__ q1f,
                              __half* __restrict__ q1h, __half* __restrict__ q1l,
                              __half* __restrict__ k1h, __half* __restrict__ k1l) {
    long idx = (long)blockIdx.x * blockDim.x + threadIdx.x;
    long td = idx % ((long)T_ * D_);
    float p = pe[td];
    float a = q[idx] + p;
    q1f[idx] = a;
    __half ah = __float2half_rn(a);
    q1h[idx] = ah;
    q1l[idx] = __float2half_rn(a - __half2float(ah));
    float bb = a + p;                      // k1 = q1 + pe (source bug kept)
    __half bh = __float2half_rn(bb);
    k1h[idx] = bh;
    k1l[idx] = __float2half_rn(bb - __half2float(bh));
}

// single fused conversion kernel: all weights + cmax init
__global__ void cvt_all_kernel(const float* __restrict__ wq, const float* __restrict__ wk,
                               const float* __restrict__ wv, const float* __restrict__ f1,
                               const float* __restrict__ f2,
                               __half* __restrict__ wqh, __half* __restrict__ wql,
                               __half* __restrict__ wkh, __half* __restrict__ wkl,
                               __half* __restrict__ wvh,
                               __half* __restrict__ f1h, __half* __restrict__ f2h,
                               float* __restrict__ cmaxp) {
    constexpr int DD = D_ * D_;
    constexpr int DF = D_ * FF_;
    int i = blockIdx.x * blockDim.x + threadIdx.x;
    if (i < DD) {
        float x = wq[i];
        __half h = __float2half_rn(x);
        wqh[i] = h;
        wql[i] = __float2half_rn(x - __half2float(h));
    } else if (i < 2 * DD) {
        int j = i - DD;
        float x = wk[j];
        __half h = __float2half_rn(x);
        wkh[j] = h;
        wkl[j] = __float2half_rn(x - __half2float(h));
    } else if (i < 3 * DD) {
        int j = i - 2 * DD;
        wvh[j] = __float2half_rn(wv[j]);
    } else if (i < 3 * DD + DF) {
        int j = i - 3 * DD;
        f1h[j] = __float2half_rn(f1[j]);
    } else if (i < 3 * DD + 2 * DF) {
        int j = i - 3 * DD - DF;
        f2h[j] = __float2half_rn(f2[j]);
    } else if (i < 3 * DD + 2 * DF + HB_ * T_) {
        cmaxp[i - 3 * DD - 2 * DF] = -INFINITY;
    }
}

// ---------------- launch -----------------------------------------------------
extern "C" void kernel_launch(void* const* d_in, const int* in_sizes, int n_in,
                              void* d_out, int out_size) {
    const float* queries = (const float*)d_in[0];
    const int*   qmasks  = (const int*)d_in[2];
    const float* W_Q = (const float*)d_in[4];
    const float* W_K = (const float*)d_in[5];
    const float* W_V = (const float*)d_in[6];
    const float* fw1 = (const float*)d_in[7];
    const float* fw2 = (const float*)d_in[8];
    float* out = (float*)d_out;

    float *pe, *q1f, *S, *cmax, *R;
    __half *Pb;
    __half *q1h, *q1l, *k1h, *k1l, *Qh, *Ql, *Kh, *Kl, *Vh, *Rh, *Hd;
    __half *wqh, *wql, *wkh, *wkl, *wvh, *f1h, *f2h;
    cudaGetSymbolAddress((void**)&pe,  g_pe);
    cudaGetSymbolAddress((void**)&q1f, g_q1);
    cudaGetSymbolAddress((void**)&q1h, g_q1h);
    cudaGetSymbolAddress((void**)&q1l, g_q1l);
    cudaGetSymbolAddress((void**)&k1h, g_k1h);
    cudaGetSymbolAddress((void**)&k1l, g_k1l);
    cudaGetSymbolAddress((void**)&Qh,  g_Qh);
    cudaGetSymbolAddress((void**)&Ql,  g_Ql);
    cudaGetSymbolAddress((void**)&Kh,  g_Kh);
    cudaGetSymbolAddress((void**)&Kl,  g_Kl);
    cudaGetSymbolAddress((void**)&Vh,  g_Vh);
    cudaGetSymbolAddress((void**)&S,   g_S);
    cudaGetSymbolAddress((void**)&Pb,  g_P);
    cudaGetSymbolAddress((void**)&cmax, g_cmax);
    cudaGetSymbolAddress((void**)&R,   g_R);
    cudaGetSymbolAddress((void**)&Rh,  g_Rh);
    cudaGetSymbolAddress((void**)&Hd,  g_H);
    cudaGetSymbolAddress((void**)&wqh, g_wqh);
    cudaGetSymbolAddress((void**)&wql, g_wql);
    cudaGetSymbolAddress((void**)&wkh, g_wkh);
    cudaGetSymbolAddress((void**)&wkl, g_wkl);
    cudaGetSymbolAddress((void**)&wvh, g_wvh);
    cudaGetSymbolAddress((void**)&f1h, g_f1h);
    cudaGetSymbolAddress((void**)&f2h, g_f2h);

    const long TD = (long)T_ * D_;
    const long TT = (long)T_ * T_;

    constexpr int SM_PLAIN = smem4(false, false, 3);  // 56832
    constexpr int SM_SPL3  = smem4(false, true,  3);  // 113664 (2 CTAs: 227328)
    constexpr int SM_SPL1  = smem4(true,  true,  2);  // 81920

    cudaFuncSetAttribute((const void*)mma4<false, true,  2, false, 3, true>,
                         cudaFuncAttributeMaxDynamicSharedMemorySize, SM_SPL3);
    cudaFuncSetAttribute((const void*)mma4<true,  true,  0, true,  2, false>,
                         cudaFuncAttributeMaxDynamicSharedMemorySize, SM_SPL1);
    cudaFuncSetAttribute((const void*)mma4<false, false, 1, false, 3, false>,
                         cudaFuncAttributeMaxDynamicSharedMemorySize, SM_PLAIN);
    cudaFuncSetAttribute((const void*)mma4<false, false, 0, false, 3, false>,
                         cudaFuncAttributeMaxDynamicSharedMemorySize, SM_PLAIN);
    cudaFuncSetAttribute((const void*)fsav_kernel,
                         cudaFuncAttributeMaxDynamicSharedMemorySize, FS_SMEM);

    // 1) posenc + all conversions (+cmax init)
    pe_kernel<<<(T_ * D_ + 255) / 256, 256>>>(pe);
    addpe2_kernel<<<(B_ * T_ * D_) / 256, 256>>>(queries, pe, q1f, q1h, q1l, k1h, k1l);
    {
        int n = 3 * D_ * D_ + 2 * D_ * FF_ + HB_ * T_;
        cvt_all_kernel<<<(n + 255) / 256, 256>>>(W_Q, W_K, W_V, fw1, fw2,
                                                 wqh, wql, wkh, wkl, wvh, f1h, f2h, cmax);
    }

    // 2) Q and K projections batched in one DUAL launch (fp16 split, 3-stage)
    {
        dim3 g(D_ / 128, (B_ * T_) / 128, 2);
        mma4<false, true, 2, false, 3, true><<<g, 256, SM_SPL3>>>(
            q1h, q1l, 0, 0, D_, wqh, wql, 0, 0, D_,
            nullptr, Qh, Ql, 0, 0, D_, nullptr, 0, 0, 0, nullptr, nullptr, 1, D_, 1.f, 0,
            k1h, k1l, wkh, wkl, Kh, Kl);
    }

    // 3) V projection: V = Kp @ W_V (bug kept) -> fp16 (3-stage)
    {
        dim3 g(D_ / 128, (B_ * T_) / 128, 1);
        mma4<false, false, 1, false, 3, false><<<g, 256, SM_PLAIN>>>(
            Kh, nullptr, 0, 0, D_, wvh, nullptr, 0, 0, D_,
            nullptr, Vh, nullptr, 0, 0, D_, nullptr, 0, 0, 0, nullptr, nullptr, 1, D_, 1.f, 0,
            nullptr, nullptr, nullptr, nullptr, nullptr, nullptr);
    }

    // 4) scores (fp16 split, B=[N][K]) -> fp32 S + fused column-max atomics
    //    masked rows (q >= qmasks[b]) feed colmax only; their S stores skipped
    {
        dim3 g(T_ / 128, T_ / 128, HB_);
        mma4<true, true, 0, true, 2, false><<<g, 256, SM_SPL1>>>(
            Qh, Ql, DH_, TD, D_,
            Kh, Kl, DH_, TD, D_,
            S, nullptr, nullptr, (long)B_ * TT, TT, T_,
            nullptr, 0, 0, 0, cmax, qmasks,
            B_, DH_, 0.125f, 0,
            nullptr, nullptr, nullptr, nullptr, nullptr, nullptr);
    }

    // 5) fused two-pass softmax + AV with exp caching and qmask skipping
    {
        dim3 g(T_ / 128, HB_);
        fsav_kernel<<<g, 256, FS_SMEM>>>(S, Pb, cmax, Vh, q1f, qmasks, R, Rh);
    }

    // 6) FFN1: hidden = relu(R @ fw1) -> fp16 (3-stage)
    {
        dim3 g(FF_ / 128, (B_ * T_) / 128, 1);
        mma4<false, false, 1, false, 3, false><<<g, 256, SM_PLAIN>>>(
            Rh, nullptr, 0, 0, D_, f1h, nullptr, 0, 0, FF_,
            nullptr, Hd, nullptr, 0, 0, FF_, nullptr, 0, 0, 0, nullptr, nullptr, 1, D_, 1.f, 1,
            nullptr, nullptr, nullptr, nullptr, nullptr, nullptr);
    }

    // 7) FFN2: out = R + hidden @ fw2 -> fp32 (3-stage)
    {
        dim3 g(D_ / 128, (B_ * T_) / 128, 1);
        mma4<false, false, 0, false, 3, false><<<g, 256, SM_PLAIN>>>(
            Hd, nullptr, 0, 0, FF_, f2h, nullptr, 0, 0, D_,
            out, nullptr, nullptr, 0, 0, D_, R, 0, 0, D_, nullptr, nullptr, 1, FF_, 1.f, 0,
            nullptr, nullptr, nullptr, nullptr, nullptr, nullptr);
    }
}